// round 1
// baseline (speedup 1.0000x reference)
#include <cuda_runtime.h>
#include <cuda_bf16.h>
#include <math.h>

// Problem constants
#define D_MODEL 1024
#define N_HEADS 16
#define D_K     64
#define LATENT  256
#define BATCH   2
#define SEQ     2048
#define ROWS    (BATCH * SEQ)   // 4096 flattened rows

// Scratch (device globals — no allocation allowed)
__device__ float g_Q[ROWS * D_MODEL];
__device__ float g_K[ROWS * D_MODEL];
__device__ float g_V[ROWS * D_MODEL];
__device__ float g_lat[ROWS * LATENT];
__device__ float g_O[ROWS * D_MODEL];

// ---------------------------------------------------------------------------
// Tiled fp32 GEMM: C[M,N] = A[M,K] @ W[K,N] + bias[N]
// 64x64 tile, BK=16, 256 threads, 4x4 microtile per thread.
// ---------------------------------------------------------------------------
#define TS 64
#define KS 16

__global__ __launch_bounds__(256) void gemm_bias_kernel(
    const float* __restrict__ A, const float* __restrict__ W,
    const float* __restrict__ bias, float* __restrict__ C,
    int M, int N, int K)
{
    __shared__ float As[KS][TS];   // transposed A tile: As[k][m]
    __shared__ float Ws[KS][TS];   // W tile: Ws[k][n]

    const int tid = threadIdx.x;
    const int tx  = tid & 15;       // 0..15 (n micro)
    const int ty  = tid >> 4;       // 0..15 (m micro)
    const int m0  = blockIdx.y * TS;
    const int n0  = blockIdx.x * TS;

    // loader indices
    const int ar = tid >> 2;        // 0..63 row within A tile
    const int ac = (tid & 3) * 4;   // 0,4,8,12 col within A tile
    const int wr = tid >> 4;        // 0..15 row within W tile
    const int wc = (tid & 15) * 4;  // 0..60

    float acc[4][4];
    #pragma unroll
    for (int i = 0; i < 4; i++)
        #pragma unroll
        for (int j = 0; j < 4; j++) acc[i][j] = 0.f;

    for (int k0 = 0; k0 < K; k0 += KS) {
        float4 av = *(const float4*)&A[(m0 + ar) * K + k0 + ac];
        As[ac + 0][ar] = av.x;
        As[ac + 1][ar] = av.y;
        As[ac + 2][ar] = av.z;
        As[ac + 3][ar] = av.w;
        *(float4*)&Ws[wr][wc] = *(const float4*)&W[(k0 + wr) * N + n0 + wc];
        __syncthreads();

        #pragma unroll
        for (int k = 0; k < KS; k++) {
            float4 a = *(const float4*)&As[k][ty * 4];
            float4 w = *(const float4*)&Ws[k][tx * 4];
            float ai[4] = {a.x, a.y, a.z, a.w};
            float wi[4] = {w.x, w.y, w.z, w.w};
            #pragma unroll
            for (int i = 0; i < 4; i++)
                #pragma unroll
                for (int j = 0; j < 4; j++)
                    acc[i][j] = fmaf(ai[i], wi[j], acc[i][j]);
        }
        __syncthreads();
    }

    #pragma unroll
    for (int i = 0; i < 4; i++) {
        int row = m0 + ty * 4 + i;
        #pragma unroll
        for (int j = 0; j < 4; j++) {
            int col = n0 + tx * 4 + j;
            C[row * N + col] = acc[i][j] + bias[col];
        }
    }
}

// ---------------------------------------------------------------------------
// Causal flash attention (fp32). One block = 64 query rows for one (b, h).
// 64 threads; thread r owns query row r of the tile.
// q[64] and acc[64] in registers; K/V tiles in smem (broadcast reads);
// scores staged transposed in smem (conflict-free).
// ---------------------------------------------------------------------------
__global__ __launch_bounds__(64) void attn_kernel(
    const float* __restrict__ Q, const float* __restrict__ Km,
    const float* __restrict__ Vm, float* __restrict__ O)
{
    __shared__ float Ks[64][64];
    __shared__ float Vs[64][64];
    __shared__ float Ss[64][64];   // transposed: Ss[j][r]

    const int r    = threadIdx.x;        // 0..63
    const int tile = blockIdx.x;         // 0..31
    const int h    = blockIdx.y;         // 0..15
    const int b    = blockIdx.z;         // 0..1

    const int qrow = tile * 64 + r;      // row within sequence
    const int base = b * SEQ;            // flattened row base for this batch
    const float scale = 0.125f;          // 1/sqrt(64)

    // Load this thread's query row into registers
    const float* qptr = Q + (size_t)(base + qrow) * D_MODEL + h * D_K;
    float q[64];
    #pragma unroll
    for (int d4 = 0; d4 < 64; d4 += 4) {
        float4 v = *(const float4*)(qptr + d4);
        q[d4 + 0] = v.x; q[d4 + 1] = v.y; q[d4 + 2] = v.z; q[d4 + 3] = v.w;
    }

    float acc[64];
    #pragma unroll
    for (int d = 0; d < 64; d++) acc[d] = 0.f;
    float m = -1e30f;
    float l = 0.f;

    for (int t = 0; t <= tile; t++) {
        const int j0 = t * 64;
        // Cooperative K/V tile load (float4, coalesced)
        #pragma unroll
        for (int it = 0; it < 16; it++) {
            int idx = it * 64 + r;              // float4 index 0..1023
            int j   = idx >> 4;                 // 0..63
            int d4  = (idx & 15) * 4;           // 0..60
            size_t g = (size_t)(base + j0 + j) * D_MODEL + h * D_K + d4;
            *(float4*)&Ks[j][d4] = *(const float4*)&Km[g];
            *(float4*)&Vs[j][d4] = *(const float4*)&Vm[g];
        }
        __syncthreads();

        const bool diag = (t == tile);
        float tmax = -1e30f;
        for (int j = 0; j < 64; j++) {
            float s = 0.f;
            #pragma unroll
            for (int d4 = 0; d4 < 64; d4 += 4) {
                float4 kv = *(const float4*)&Ks[j][d4];
                s = fmaf(q[d4 + 0], kv.x, s);
                s = fmaf(q[d4 + 1], kv.y, s);
                s = fmaf(q[d4 + 2], kv.z, s);
                s = fmaf(q[d4 + 3], kv.w, s);
            }
            s *= scale;
            if (diag && (j0 + j > qrow)) s = -1e30f;
            Ss[j][r] = s;
            tmax = fmaxf(tmax, s);
        }

        float mn = fmaxf(m, tmax);
        float c  = __expf(m - mn);
        l *= c;
        #pragma unroll
        for (int d = 0; d < 64; d++) acc[d] *= c;

        for (int j = 0; j < 64; j++) {
            float p = __expf(Ss[j][r] - mn);
            l += p;
            #pragma unroll
            for (int d4 = 0; d4 < 64; d4 += 4) {
                float4 vv = *(const float4*)&Vs[j][d4];
                acc[d4 + 0] = fmaf(p, vv.x, acc[d4 + 0]);
                acc[d4 + 1] = fmaf(p, vv.y, acc[d4 + 1]);
                acc[d4 + 2] = fmaf(p, vv.z, acc[d4 + 2]);
                acc[d4 + 3] = fmaf(p, vv.w, acc[d4 + 3]);
            }
        }
        m = mn;
        __syncthreads();
    }

    const float inv = 1.f / l;
    float* optr = O + (size_t)(base + qrow) * D_MODEL + h * D_K;
    #pragma unroll
    for (int d4 = 0; d4 < 64; d4 += 4) {
        float4 o;
        o.x = acc[d4 + 0] * inv;
        o.y = acc[d4 + 1] * inv;
        o.z = acc[d4 + 2] * inv;
        o.w = acc[d4 + 3] * inv;
        *(float4*)(optr + d4) = o;
    }
}

// ---------------------------------------------------------------------------
// Launch
// ---------------------------------------------------------------------------
extern "C" void kernel_launch(void* const* d_in, const int* in_sizes, int n_in,
                              void* d_out, int out_size)
{
    const float* queries = (const float*)d_in[0];
    const float* keys    = (const float*)d_in[1];
    // d_in[2] = values (unused by reference)
    const float* Wq = (const float*)d_in[3];
    const float* bq = (const float*)d_in[4];
    const float* Wd = (const float*)d_in[5];
    const float* bd = (const float*)d_in[6];
    const float* Wk = (const float*)d_in[7];
    const float* bk = (const float*)d_in[8];
    const float* Wv = (const float*)d_in[9];
    const float* bv = (const float*)d_in[10];
    const float* Wo = (const float*)d_in[11];
    const float* bo = (const float*)d_in[12];
    float* out = (float*)d_out;

    float *pQ, *pK, *pV, *pLat, *pO;
    cudaGetSymbolAddress((void**)&pQ,   g_Q);
    cudaGetSymbolAddress((void**)&pK,   g_K);
    cudaGetSymbolAddress((void**)&pV,   g_V);
    cudaGetSymbolAddress((void**)&pLat, g_lat);
    cudaGetSymbolAddress((void**)&pO,   g_O);

    dim3 blk(256);

    // 1) latent = keys @ Wd + bd     [4096,1024]x[1024,256]
    gemm_bias_kernel<<<dim3(LATENT / TS, ROWS / TS), blk>>>(
        keys, Wd, bd, pLat, ROWS, LATENT, D_MODEL);

    // 2) Q = queries @ Wq + bq       [4096,1024]x[1024,1024]
    gemm_bias_kernel<<<dim3(D_MODEL / TS, ROWS / TS), blk>>>(
        queries, Wq, bq, pQ, ROWS, D_MODEL, D_MODEL);

    // 3) K = latent @ Wk + bk        [4096,256]x[256,1024]
    gemm_bias_kernel<<<dim3(D_MODEL / TS, ROWS / TS), blk>>>(
        pLat, Wk, bk, pK, ROWS, D_MODEL, LATENT);

    // 4) V = latent @ Wv + bv
    gemm_bias_kernel<<<dim3(D_MODEL / TS, ROWS / TS), blk>>>(
        pLat, Wv, bv, pV, ROWS, D_MODEL, LATENT);

    // 5) causal attention -> g_O
    attn_kernel<<<dim3(SEQ / 64, N_HEADS, BATCH), dim3(64)>>>(pQ, pK, pV, pO);

    // 6) out = O @ Wo + bo
    gemm_bias_kernel<<<dim3(D_MODEL / TS, ROWS / TS), blk>>>(
        pO, Wo, bo, out, ROWS, D_MODEL, D_MODEL);
}

// round 2
// speedup vs baseline: 1.1764x; 1.1764x over previous
#include <cuda_runtime.h>
#include <cuda_bf16.h>
#include <math.h>

// Problem constants
#define D_MODEL 1024
#define N_HEADS 16
#define D_K     64
#define LATENT  256
#define BATCH   2
#define SEQ     2048
#define ROWS    (BATCH * SEQ)   // 4096 flattened rows

// Scratch (device globals — no allocation allowed)
__device__ float g_Q[ROWS * D_MODEL];
__device__ float g_K[ROWS * D_MODEL];
__device__ float g_V[ROWS * D_MODEL];
__device__ float g_lat[ROWS * LATENT];
__device__ float g_O[ROWS * D_MODEL];

// ---------------------------------------------------------------------------
// Tiled fp32 GEMM: C[M,N] = A[M,K] @ W[K,N] + bias[N]
// 64x64 tile, BK=16, 256 threads, 4x4 microtile per thread.
// ---------------------------------------------------------------------------
#define TS 64
#define KS 16

__global__ __launch_bounds__(256) void gemm_bias_kernel(
    const float* __restrict__ A, const float* __restrict__ W,
    const float* __restrict__ bias, float* __restrict__ C,
    int M, int N, int K)
{
    __shared__ float As[KS][TS];   // transposed A tile: As[k][m]
    __shared__ float Ws[KS][TS];   // W tile: Ws[k][n]

    const int tid = threadIdx.x;
    const int tx  = tid & 15;       // 0..15 (n micro)
    const int ty  = tid >> 4;       // 0..15 (m micro)
    const int m0  = blockIdx.y * TS;
    const int n0  = blockIdx.x * TS;

    const int ar = tid >> 2;        // 0..63 row within A tile
    const int ac = (tid & 3) * 4;   // 0,4,8,12 col within A tile
    const int wr = tid >> 4;        // 0..15 row within W tile
    const int wc = (tid & 15) * 4;  // 0..60

    float acc[4][4];
    #pragma unroll
    for (int i = 0; i < 4; i++)
        #pragma unroll
        for (int j = 0; j < 4; j++) acc[i][j] = 0.f;

    for (int k0 = 0; k0 < K; k0 += KS) {
        float4 av = *(const float4*)&A[(m0 + ar) * K + k0 + ac];
        As[ac + 0][ar] = av.x;
        As[ac + 1][ar] = av.y;
        As[ac + 2][ar] = av.z;
        As[ac + 3][ar] = av.w;
        *(float4*)&Ws[wr][wc] = *(const float4*)&W[(k0 + wr) * N + n0 + wc];
        __syncthreads();

        #pragma unroll
        for (int k = 0; k < KS; k++) {
            float4 a = *(const float4*)&As[k][ty * 4];
            float4 w = *(const float4*)&Ws[k][tx * 4];
            float ai[4] = {a.x, a.y, a.z, a.w};
            float wi[4] = {w.x, w.y, w.z, w.w};
            #pragma unroll
            for (int i = 0; i < 4; i++)
                #pragma unroll
                for (int j = 0; j < 4; j++)
                    acc[i][j] = fmaf(ai[i], wi[j], acc[i][j]);
        }
        __syncthreads();
    }

    #pragma unroll
    for (int i = 0; i < 4; i++) {
        int row = m0 + ty * 4 + i;
        #pragma unroll
        for (int j = 0; j < 4; j++) {
            int col = n0 + tx * 4 + j;
            C[row * N + col] = acc[i][j] + bias[col];
        }
    }
}

// ---------------------------------------------------------------------------
// Causal flash attention (fp32), GEMM-style tiles.
// 256 threads/block, 64 query rows per block. Both QK^T and PV are 64x64x64
// smem GEMMs with 4x4 microtiles. Online softmax row stats replicated across
// the 16 lanes (tx) that share a row; butterfly shuffles for row reductions.
// Dynamic smem: Qt[64][64] + Kt[64][64] + Vs[64][64] + Ps[64][68].
// ---------------------------------------------------------------------------
#define PS_LD 68

__global__ __launch_bounds__(256) void attn_kernel(
    const float* __restrict__ Q, const float* __restrict__ Km,
    const float* __restrict__ Vm, float* __restrict__ O)
{
    extern __shared__ float smem[];
    float* Qt = smem;                  // [64][64] transposed: Qt[d][r]
    float* Kt = Qt + 64 * 64;          // [64][64] transposed: Kt[d][j]
    float* Vs = Kt + 64 * 64;          // [64][64]            Vs[j][d]
    float* Ps = Vs + 64 * 64;          // [64][PS_LD]         Ps[r][j]

    const int tid = threadIdx.x;
    const int tx  = tid & 15;          // 0..15
    const int ty  = tid >> 4;          // 0..15
    const int tile = gridDim.x - 1 - blockIdx.x;  // longest blocks first
    const int h    = blockIdx.y;
    const int b    = blockIdx.z;
    const int base = b * SEQ;
    const float scale = 0.125f;

    // ---- Load Q tile (transposed) ----
    #pragma unroll
    for (int it = 0; it < 4; it++) {
        int idx = it * 256 + tid;          // float4 index 0..1023
        int r   = idx >> 4;                // 0..63 row within tile
        int d4  = (idx & 15) * 4;          // 0..60
        size_t g = (size_t)(base + tile * 64 + r) * D_MODEL + h * D_K + d4;
        float4 v = *(const float4*)&Q[g];
        Qt[(d4 + 0) * 64 + r] = v.x;
        Qt[(d4 + 1) * 64 + r] = v.y;
        Qt[(d4 + 2) * 64 + r] = v.z;
        Qt[(d4 + 3) * 64 + r] = v.w;
    }

    float oacc[4][4];
    #pragma unroll
    for (int i = 0; i < 4; i++)
        #pragma unroll
        for (int j = 0; j < 4; j++) oacc[i][j] = 0.f;
    float mrow[4], lrow[4];
    #pragma unroll
    for (int i = 0; i < 4; i++) { mrow[i] = -1e30f; lrow[i] = 0.f; }

    const float4* Qt4 = (const float4*)Qt;
    const float4* Kt4 = (const float4*)Kt;
    const float4* Vs4 = (const float4*)Vs;

    for (int t = 0; t <= tile; t++) {
        __syncthreads();   // previous iteration's Kt/Vs reads done
        // ---- Load K (transposed) and V tiles ----
        #pragma unroll
        for (int it = 0; it < 4; it++) {
            int idx = it * 256 + tid;
            int j   = idx >> 4;
            int d4  = (idx & 15) * 4;
            size_t g = (size_t)(base + t * 64 + j) * D_MODEL + h * D_K + d4;
            float4 kv = *(const float4*)&Km[g];
            Kt[(d4 + 0) * 64 + j] = kv.x;
            Kt[(d4 + 1) * 64 + j] = kv.y;
            Kt[(d4 + 2) * 64 + j] = kv.z;
            Kt[(d4 + 3) * 64 + j] = kv.w;
            *(float4*)&Vs[j * 64 + d4] = *(const float4*)&Vm[g];
        }
        __syncthreads();

        // ---- S = Q @ K^T (64x64x64) ----
        float sacc[4][4];
        #pragma unroll
        for (int i = 0; i < 4; i++)
            #pragma unroll
            for (int j = 0; j < 4; j++) sacc[i][j] = 0.f;

        #pragma unroll 8
        for (int d = 0; d < 64; d++) {
            float4 qv = Qt4[d * 16 + ty];
            float4 kv = Kt4[d * 16 + tx];
            float qi[4] = {qv.x, qv.y, qv.z, qv.w};
            float ki[4] = {kv.x, kv.y, kv.z, kv.w};
            #pragma unroll
            for (int i = 0; i < 4; i++)
                #pragma unroll
                for (int j = 0; j < 4; j++)
                    sacc[i][j] = fmaf(qi[i], ki[j], sacc[i][j]);
        }

        // ---- scale + causal mask ----
        const bool diag = (t == tile);
        #pragma unroll
        for (int i = 0; i < 4; i++) {
            int r = ty * 4 + i;
            #pragma unroll
            for (int j = 0; j < 4; j++) {
                float s = sacc[i][j] * scale;
                if (diag && (tx * 4 + j > r)) s = -1e30f;
                sacc[i][j] = s;
            }
        }

        // ---- online softmax (row reductions over the 16 tx lanes) ----
        #pragma unroll
        for (int i = 0; i < 4; i++) {
            float tm = fmaxf(fmaxf(sacc[i][0], sacc[i][1]),
                             fmaxf(sacc[i][2], sacc[i][3]));
            #pragma unroll
            for (int o = 8; o >= 1; o >>= 1)
                tm = fmaxf(tm, __shfl_xor_sync(0xffffffffu, tm, o));
            float mn = fmaxf(mrow[i], tm);
            float c  = __expf(mrow[i] - mn);
            mrow[i] = mn;

            float ls = 0.f;
            #pragma unroll
            for (int j = 0; j < 4; j++) {
                float p = __expf(sacc[i][j] - mn);
                sacc[i][j] = p;       // reuse as P
                ls += p;
            }
            #pragma unroll
            for (int o = 8; o >= 1; o >>= 1)
                ls += __shfl_xor_sync(0xffffffffu, ls, o);
            lrow[i] = lrow[i] * c + ls;

            #pragma unroll
            for (int j = 0; j < 4; j++) oacc[i][j] *= c;

            // stage P row segment
            *(float4*)&Ps[(ty * 4 + i) * PS_LD + tx * 4] = *(float4*)&sacc[i][0];
        }
        __syncthreads();

        // ---- O += P @ V (64x64x64) ----
        #pragma unroll 4
        for (int j = 0; j < 64; j++) {
            float4 vv = Vs4[j * 16 + tx];
            float vi[4] = {vv.x, vv.y, vv.z, vv.w};
            float pj[4];
            #pragma unroll
            for (int i = 0; i < 4; i++)
                pj[i] = Ps[(ty * 4 + i) * PS_LD + j];
            #pragma unroll
            for (int i = 0; i < 4; i++)
                #pragma unroll
                for (int jj = 0; jj < 4; jj++)
                    oacc[i][jj] = fmaf(pj[i], vi[jj], oacc[i][jj]);
        }
    }

    // ---- write O ----
    #pragma unroll
    for (int i = 0; i < 4; i++) {
        float inv = 1.f / lrow[i];
        int row = base + tile * 64 + ty * 4 + i;
        float4 o;
        o.x = oacc[i][0] * inv;
        o.y = oacc[i][1] * inv;
        o.z = oacc[i][2] * inv;
        o.w = oacc[i][3] * inv;
        *(float4*)&O[(size_t)row * D_MODEL + h * D_K + tx * 4] = o;
    }
}

#define ATTN_SMEM ((64*64*3 + 64*PS_LD) * 4)

// ---------------------------------------------------------------------------
// Launch
// ---------------------------------------------------------------------------
extern "C" void kernel_launch(void* const* d_in, const int* in_sizes, int n_in,
                              void* d_out, int out_size)
{
    const float* queries = (const float*)d_in[0];
    const float* keys    = (const float*)d_in[1];
    // d_in[2] = values (unused by reference)
    const float* Wq = (const float*)d_in[3];
    const float* bq = (const float*)d_in[4];
    const float* Wd = (const float*)d_in[5];
    const float* bd = (const float*)d_in[6];
    const float* Wk = (const float*)d_in[7];
    const float* bk = (const float*)d_in[8];
    const float* Wv = (const float*)d_in[9];
    const float* bv = (const float*)d_in[10];
    const float* Wo = (const float*)d_in[11];
    const float* bo = (const float*)d_in[12];
    float* out = (float*)d_out;

    float *pQ, *pK, *pV, *pLat, *pO;
    cudaGetSymbolAddress((void**)&pQ,   g_Q);
    cudaGetSymbolAddress((void**)&pK,   g_K);
    cudaGetSymbolAddress((void**)&pV,   g_V);
    cudaGetSymbolAddress((void**)&pLat, g_lat);
    cudaGetSymbolAddress((void**)&pO,   g_O);

    cudaFuncSetAttribute(attn_kernel,
                         cudaFuncAttributeMaxDynamicSharedMemorySize, ATTN_SMEM);

    dim3 blk(256);

    // 1) latent = keys @ Wd + bd     [4096,1024]x[1024,256]
    gemm_bias_kernel<<<dim3(LATENT / TS, ROWS / TS), blk>>>(
        keys, Wd, bd, pLat, ROWS, LATENT, D_MODEL);

    // 2) Q = queries @ Wq + bq       [4096,1024]x[1024,1024]
    gemm_bias_kernel<<<dim3(D_MODEL / TS, ROWS / TS), blk>>>(
        queries, Wq, bq, pQ, ROWS, D_MODEL, D_MODEL);

    // 3) K = latent @ Wk + bk        [4096,256]x[256,1024]
    gemm_bias_kernel<<<dim3(D_MODEL / TS, ROWS / TS), blk>>>(
        pLat, Wk, bk, pK, ROWS, D_MODEL, LATENT);

    // 4) V = latent @ Wv + bv
    gemm_bias_kernel<<<dim3(D_MODEL / TS, ROWS / TS), blk>>>(
        pLat, Wv, bv, pV, ROWS, D_MODEL, LATENT);

    // 5) causal attention -> g_O
    attn_kernel<<<dim3(SEQ / 64, N_HEADS, BATCH), dim3(256), ATTN_SMEM>>>(
        pQ, pK, pV, pO);

    // 6) out = O @ Wo + bo
    gemm_bias_kernel<<<dim3(D_MODEL / TS, ROWS / TS), blk>>>(
        pO, Wo, bo, out, ROWS, D_MODEL, D_MODEL);
}

// round 4
// speedup vs baseline: 1.3189x; 1.1211x over previous
#include <cuda_runtime.h>
#include <cuda_bf16.h>
#include <math.h>

// Problem constants
#define D_MODEL 1024
#define N_HEADS 16
#define D_K     64
#define LATENT  256
#define BATCH   2
#define SEQ     2048
#define ROWS    (BATCH * SEQ)   // 4096 flattened rows

// Scratch (device globals — no allocation allowed)
__device__ float g_Q[ROWS * D_MODEL];
__device__ float g_K[ROWS * D_MODEL];
__device__ float g_V[ROWS * D_MODEL];
__device__ float g_lat[ROWS * LATENT];
__device__ float g_O[ROWS * D_MODEL];

// ---------------------------------------------------------------------------
// Tiled fp32 GEMM: C[M,N] = A[M,K] @ W[K,N] + bias[N]
// 64x64 tile, BK=16, 256 threads, 4x4 microtile per thread.
// ---------------------------------------------------------------------------
#define TS 64
#define KS 16

__global__ __launch_bounds__(256) void gemm_bias_kernel(
    const float* __restrict__ A, const float* __restrict__ W,
    const float* __restrict__ bias, float* __restrict__ C,
    int M, int N, int K)
{
    __shared__ float As[KS][TS];   // transposed A tile: As[k][m]
    __shared__ float Ws[KS][TS];   // W tile: Ws[k][n]

    const int tid = threadIdx.x;
    const int tx  = tid & 15;       // 0..15 (n micro)
    const int ty  = tid >> 4;       // 0..15 (m micro)
    const int m0  = blockIdx.y * TS;
    const int n0  = blockIdx.x * TS;

    const int ar = tid >> 2;        // 0..63 row within A tile
    const int ac = (tid & 3) * 4;   // 0,4,8,12 col within A tile
    const int wr = tid >> 4;        // 0..15 row within W tile
    const int wc = (tid & 15) * 4;  // 0..60

    float acc[4][4];
    #pragma unroll
    for (int i = 0; i < 4; i++)
        #pragma unroll
        for (int j = 0; j < 4; j++) acc[i][j] = 0.f;

    for (int k0 = 0; k0 < K; k0 += KS) {
        float4 av = *(const float4*)&A[(size_t)(m0 + ar) * K + k0 + ac];
        As[ac + 0][ar] = av.x;
        As[ac + 1][ar] = av.y;
        As[ac + 2][ar] = av.z;
        As[ac + 3][ar] = av.w;
        *(float4*)&Ws[wr][wc] = *(const float4*)&W[(size_t)(k0 + wr) * N + n0 + wc];
        __syncthreads();

        #pragma unroll
        for (int k = 0; k < KS; k++) {
            float4 a = *(const float4*)&As[k][ty * 4];
            float4 w = *(const float4*)&Ws[k][tx * 4];
            float ai[4] = {a.x, a.y, a.z, a.w};
            float wi[4] = {w.x, w.y, w.z, w.w};
            #pragma unroll
            for (int i = 0; i < 4; i++)
                #pragma unroll
                for (int j = 0; j < 4; j++)
                    acc[i][j] = fmaf(ai[i], wi[j], acc[i][j]);
        }
        __syncthreads();
    }

    #pragma unroll
    for (int i = 0; i < 4; i++) {
        int row = m0 + ty * 4 + i;
        #pragma unroll
        for (int j = 0; j < 4; j++) {
            int col = n0 + tx * 4 + j;
            C[(size_t)row * N + col] = acc[i][j] + bias[col];
        }
    }
}

// ---------------------------------------------------------------------------
// Causal flash attention (fp32), GEMM-style tiles, swizzled smem.
// 256 threads, 64 query rows per block. Qt/Kt stored transposed with
// float4-cell XOR swizzle ((d>>2)&15) -> 2-way store conflicts max.
// PV reads P via broadcast LDS.128.
// ---------------------------------------------------------------------------
#define PS_LD 68

__global__ __launch_bounds__(256) void attn_kernel(
    const float* __restrict__ Q, const float* __restrict__ Km,
    const float* __restrict__ Vm, float* __restrict__ O)
{
    extern __shared__ float smem[];
    float* Qt = smem;                  // 64x64: cell(d,rg) = d*16 + (rg ^ ((d>>2)&15))
    float* Kt = Qt + 64 * 64;
    float* Vs = Kt + 64 * 64;          // [j][d] linear
    float* Ps = Vs + 64 * 64;          // [64][PS_LD]

    const int tid = threadIdx.x;
    const int tx  = tid & 15;
    const int ty  = tid >> 4;
    const int tile = gridDim.x - 1 - blockIdx.x;  // longest blocks first
    const int h    = blockIdx.y;
    const int b    = blockIdx.z;
    const int base = b * SEQ;
    const float scale = 0.125f;

    // ---- Load Q tile (transposed, swizzled) ----
    #pragma unroll
    for (int it = 0; it < 4; it++) {
        int idx = it * 256 + tid;
        int r   = idx >> 4;
        int d4  = (idx & 15) * 4;
        size_t g = (size_t)(base + tile * 64 + r) * D_MODEL + h * D_K + d4;
        float4 v = *(const float4*)&Q[g];
        float comp[4] = {v.x, v.y, v.z, v.w};
        #pragma unroll
        for (int c = 0; c < 4; c++) {
            int d = d4 + c;
            int cell = d * 16 + ((r >> 2) ^ ((d >> 2) & 15));
            Qt[cell * 4 + (r & 3)] = comp[c];
        }
    }

    float oacc[4][4];
    #pragma unroll
    for (int i = 0; i < 4; i++)
        #pragma unroll
        for (int j = 0; j < 4; j++) oacc[i][j] = 0.f;
    float mrow[4], lrow[4];
    #pragma unroll
    for (int i = 0; i < 4; i++) { mrow[i] = -1e30f; lrow[i] = 0.f; }

    const float4* Qt4 = (const float4*)Qt;
    const float4* Kt4 = (const float4*)Kt;
    const float4* Vs4 = (const float4*)Vs;
    const float4* Ps4 = (const float4*)Ps;

    for (int t = 0; t <= tile; t++) {
        __syncthreads();
        // ---- Load K (transposed, swizzled) and V tiles ----
        #pragma unroll
        for (int it = 0; it < 4; it++) {
            int idx = it * 256 + tid;
            int j   = idx >> 4;
            int d4  = (idx & 15) * 4;
            size_t g = (size_t)(base + t * 64 + j) * D_MODEL + h * D_K + d4;
            float4 kv = *(const float4*)&Km[g];
            float comp[4] = {kv.x, kv.y, kv.z, kv.w};
            #pragma unroll
            for (int c = 0; c < 4; c++) {
                int d = d4 + c;
                int cell = d * 16 + ((j >> 2) ^ ((d >> 2) & 15));
                Kt[cell * 4 + (j & 3)] = comp[c];
            }
            *(float4*)&Vs[j * 64 + d4] = *(const float4*)&Vm[g];
        }
        __syncthreads();

        // ---- S = Q @ K^T (64x64x64) ----
        float sacc[4][4];
        #pragma unroll
        for (int i = 0; i < 4; i++)
            #pragma unroll
            for (int j = 0; j < 4; j++) sacc[i][j] = 0.f;

        #pragma unroll 8
        for (int d = 0; d < 64; d++) {
            int swz = (d >> 2) & 15;
            float4 qv = Qt4[d * 16 + (ty ^ swz)];
            float4 kv = Kt4[d * 16 + (tx ^ swz)];
            float qi[4] = {qv.x, qv.y, qv.z, qv.w};
            float ki[4] = {kv.x, kv.y, kv.z, kv.w};
            #pragma unroll
            for (int i = 0; i < 4; i++)
                #pragma unroll
                for (int j = 0; j < 4; j++)
                    sacc[i][j] = fmaf(qi[i], ki[j], sacc[i][j]);
        }

        // ---- scale + causal mask ----
        const bool diag = (t == tile);
        #pragma unroll
        for (int i = 0; i < 4; i++) {
            int r = ty * 4 + i;
            #pragma unroll
            for (int j = 0; j < 4; j++) {
                float s = sacc[i][j] * scale;
                if (diag && (tx * 4 + j > r)) s = -1e30f;
                sacc[i][j] = s;
            }
        }

        // ---- online softmax (row reductions over 16 tx lanes) ----
        #pragma unroll
        for (int i = 0; i < 4; i++) {
            float tm = fmaxf(fmaxf(sacc[i][0], sacc[i][1]),
                             fmaxf(sacc[i][2], sacc[i][3]));
            #pragma unroll
            for (int o = 8; o >= 1; o >>= 1)
                tm = fmaxf(tm, __shfl_xor_sync(0xffffffffu, tm, o));
            float mn = fmaxf(mrow[i], tm);
            float c  = __expf(mrow[i] - mn);
            mrow[i] = mn;

            float ls = 0.f;
            #pragma unroll
            for (int j = 0; j < 4; j++) {
                float p = __expf(sacc[i][j] - mn);
                sacc[i][j] = p;
                ls += p;
            }
            #pragma unroll
            for (int o = 8; o >= 1; o >>= 1)
                ls += __shfl_xor_sync(0xffffffffu, ls, o);
            lrow[i] = lrow[i] * c + ls;

            #pragma unroll
            for (int j = 0; j < 4; j++) oacc[i][j] *= c;

            *(float4*)&Ps[(ty * 4 + i) * PS_LD + tx * 4] = *(float4*)&sacc[i][0];
        }
        __syncthreads();

        // ---- O += P @ V (64x64x64), P via broadcast LDS.128 ----
        #pragma unroll 2
        for (int jq = 0; jq < 16; jq++) {
            float4 p4[4];
            #pragma unroll
            for (int i = 0; i < 4; i++)
                p4[i] = Ps4[(ty * 4 + i) * 17 + jq];
            #pragma unroll
            for (int jj = 0; jj < 4; jj++) {
                float4 vv = Vs4[(jq * 4 + jj) * 16 + tx];
                float vi[4] = {vv.x, vv.y, vv.z, vv.w};
                float pj[4] = {((float*)&p4[0])[jj], ((float*)&p4[1])[jj],
                               ((float*)&p4[2])[jj], ((float*)&p4[3])[jj]};
                #pragma unroll
                for (int i = 0; i < 4; i++)
                    #pragma unroll
                    for (int cc = 0; cc < 4; cc++)
                        oacc[i][cc] = fmaf(pj[i], vi[cc], oacc[i][cc]);
            }
        }
    }

    // ---- write O ----
    #pragma unroll
    for (int i = 0; i < 4; i++) {
        float inv = 1.f / lrow[i];
        int row = base + tile * 64 + ty * 4 + i;
        float4 o;
        o.x = oacc[i][0] * inv;
        o.y = oacc[i][1] * inv;
        o.z = oacc[i][2] * inv;
        o.w = oacc[i][3] * inv;
        *(float4*)&O[(size_t)row * D_MODEL + h * D_K + tx * 4] = o;
    }
}

#define ATTN_SMEM ((64*64*3 + 64*PS_LD) * 4)

// ---------------------------------------------------------------------------
// Launch
// ---------------------------------------------------------------------------
extern "C" void kernel_launch(void* const* d_in, const int* in_sizes, int n_in,
                              void* d_out, int out_size)
{
    const float* queries = (const float*)d_in[0];
    const float* keys    = (const float*)d_in[1];
    // d_in[2] = values (unused by reference)
    const float* Wq = (const float*)d_in[3];
    const float* bq = (const float*)d_in[4];
    const float* Wd = (const float*)d_in[5];
    const float* bd = (const float*)d_in[6];
    const float* Wk = (const float*)d_in[7];
    const float* bk = (const float*)d_in[8];
    const float* Wv = (const float*)d_in[9];
    const float* bv = (const float*)d_in[10];
    const float* Wo = (const float*)d_in[11];
    const float* bo = (const float*)d_in[12];
    float* out = (float*)d_out;

    float *pQ, *pK, *pV, *pLat, *pO;
    cudaGetSymbolAddress((void**)&pQ,   g_Q);
    cudaGetSymbolAddress((void**)&pK,   g_K);
    cudaGetSymbolAddress((void**)&pV,   g_V);
    cudaGetSymbolAddress((void**)&pLat, g_lat);
    cudaGetSymbolAddress((void**)&pO,   g_O);

    cudaFuncSetAttribute(attn_kernel,
                         cudaFuncAttributeMaxDynamicSharedMemorySize, ATTN_SMEM);

    dim3 blk(256);

    // 1) latent = keys @ Wd + bd     [4096,1024]x[1024,256]
    gemm_bias_kernel<<<dim3(LATENT / TS, ROWS / TS), blk>>>(
        keys, Wd, bd, pLat, ROWS, LATENT, D_MODEL);

    // 2) Q = queries @ Wq + bq       [4096,1024]x[1024,1024]
    gemm_bias_kernel<<<dim3(D_MODEL / TS, ROWS / TS), blk>>>(
        queries, Wq, bq, pQ, ROWS, D_MODEL, D_MODEL);

    // 3) K = latent @ Wk + bk        [4096,256]x[256,1024]
    gemm_bias_kernel<<<dim3(D_MODEL / TS, ROWS / TS), blk>>>(
        pLat, Wk, bk, pK, ROWS, D_MODEL, LATENT);

    // 4) V = latent @ Wv + bv
    gemm_bias_kernel<<<dim3(D_MODEL / TS, ROWS / TS), blk>>>(
        pLat, Wv, bv, pV, ROWS, D_MODEL, LATENT);

    // 5) causal attention -> g_O
    attn_kernel<<<dim3(SEQ / 64, N_HEADS, BATCH), dim3(256), ATTN_SMEM>>>(
        pQ, pK, pV, pO);

    // 6) out = O @ Wo + bo
    gemm_bias_kernel<<<dim3(D_MODEL / TS, ROWS / TS), blk>>>(
        pO, Wo, bo, out, ROWS, D_MODEL, D_MODEL);
}

// round 6
// speedup vs baseline: 1.7466x; 1.3243x over previous
#include <cuda_runtime.h>
#include <cuda_bf16.h>
#include <math.h>
#include <stdint.h>

// Problem constants
#define D_MODEL 1024
#define N_HEADS 16
#define D_K     64
#define LATENT  256
#define BATCH   2
#define SEQ     2048
#define ROWS    (BATCH * SEQ)   // 4096

// Scratch (device globals)
__device__ float g_Q[ROWS * D_MODEL];
__device__ float g_K[ROWS * D_MODEL];
__device__ float g_V[ROWS * D_MODEL];
__device__ float g_lat[ROWS * LATENT];
__device__ float g_O[ROWS * D_MODEL];
// transposed weights [N][K] fp32
__device__ float g_WqT[D_MODEL * D_MODEL];
__device__ float g_WdT[LATENT * D_MODEL];
__device__ float g_WkT[D_MODEL * LATENT];
__device__ float g_WvT[D_MODEL * LATENT];
__device__ float g_WoT[D_MODEL * D_MODEL];

__device__ __forceinline__ uint32_t smem_u32(const void* p) {
    uint32_t a;
    asm("{ .reg .u64 t; cvta.to.shared.u64 t, %1; cvt.u32.u64 %0, t; }"
        : "=r"(a) : "l"(p));
    return a;
}

#define LDSM_X4(r0, r1, r2, r3, addr) \
    asm volatile("ldmatrix.sync.aligned.m8n8.x4.shared.b16 {%0,%1,%2,%3}, [%4];" \
        : "=r"(r0), "=r"(r1), "=r"(r2), "=r"(r3) : "r"(addr))

#define MMA_BF16(c, a, b0v, b1v) \
    asm volatile("mma.sync.aligned.m16n8k16.row.col.f32.bf16.bf16.f32 " \
        "{%0,%1,%2,%3}, {%4,%5,%6,%7}, {%8,%9}, {%0,%1,%2,%3};" \
        : "+f"((c)[0]), "+f"((c)[1]), "+f"((c)[2]), "+f"((c)[3]) \
        : "r"((a)[0]), "r"((a)[1]), "r"((a)[2]), "r"((a)[3]), "r"(b0v), "r"(b1v))

// ---------------------------------------------------------------------------
// Weight transpose: Wt[n][k] = W[k][n]
// ---------------------------------------------------------------------------
__global__ void transpose_kernel(const float* __restrict__ W,
                                 float* __restrict__ Wt, int K, int N)
{
    __shared__ float t[32][33];
    int kb = blockIdx.y * 32, nb = blockIdx.x * 32;
    int x = threadIdx.x, y = threadIdx.y;   // 32 x 8
    #pragma unroll
    for (int i = 0; i < 32; i += 8)
        t[y + i][x] = W[(size_t)(kb + y + i) * N + nb + x];
    __syncthreads();
    #pragma unroll
    for (int i = 0; i < 32; i += 8)
        Wt[(size_t)(nb + y + i) * K + kb + x] = t[x][y + i];
}

// ---------------------------------------------------------------------------
// Split-bf16 tensor-core GEMM: C[M,N] = A[M,K] @ BT[N,K]^T + bias
// 128x128 CTA tile, BK=64, 256 threads (8 warps, warp tile 32x64).
// D = Ah*Bh + Ah*Bl + Al*Bh via mma.sync.m16n8k16 bf16.
// smem tiles Ah/Al/Bh/Bl [128 rows][64 cols] bf16, 16B-unit XOR swizzle.
// ---------------------------------------------------------------------------
#define GSM_AH 0
#define GSM_AL 16384
#define GSM_BH 32768
#define GSM_BL 49152
#define GEMM_SMEM 65536

__global__ __launch_bounds__(256) void gemm_mma_kernel(
    const float* __restrict__ A, const float* __restrict__ BT,
    const float* __restrict__ bias, float* __restrict__ C,
    int M, int N, int K)
{
    extern __shared__ char sm[];
    const uint32_t sb = smem_u32(sm);
    const int tid  = threadIdx.x;
    const int lane = tid & 31;
    const int wid  = tid >> 5;
    const int wm   = (wid & 3) * 32;      // warp m offset in tile
    const int wn   = (wid >> 2) * 64;     // warp n offset in tile
    const int m0   = blockIdx.y * 128;
    const int n0   = blockIdx.x * 128;

    const int sel = lane >> 3;            // 0..3 (ldmatrix sub-matrix)
    const int l7  = lane & 7;

    float cacc[2][8][4];
    #pragma unroll
    for (int mt = 0; mt < 2; mt++)
        #pragma unroll
        for (int nt = 0; nt < 8; nt++)
            #pragma unroll
            for (int i = 0; i < 4; i++) cacc[mt][nt][i] = 0.f;

    for (int k0 = 0; k0 < K; k0 += 64) {
        // ---- load + convert + split into smem ----
        #pragma unroll
        for (int it = 0; it < 8; it++) {
            int idx = it * 256 + tid;         // 0..2047 float4 slots
            int row = idx >> 4;               // 0..127
            int c4  = (idx & 15) << 2;        // 0..60
            float4 a = *(const float4*)&A [(size_t)(m0 + row) * K + k0 + c4];
            float4 b = *(const float4*)&BT[(size_t)(n0 + row) * K + k0 + c4];
            uint32_t unit = (c4 >> 3) ^ (row & 7);
            uint32_t off  = row * 128 + (unit << 4) + ((c4 & 7) << 1);

            union { __nv_bfloat16 h[4]; uint2 u; } hh, ll;
            float av[4] = {a.x, a.y, a.z, a.w};
            #pragma unroll
            for (int c = 0; c < 4; c++) {
                hh.h[c] = __float2bfloat16(av[c]);
                ll.h[c] = __float2bfloat16(av[c] - __bfloat162float(hh.h[c]));
            }
            *(uint2*)(sm + GSM_AH + off) = hh.u;
            *(uint2*)(sm + GSM_AL + off) = ll.u;

            float bv[4] = {b.x, b.y, b.z, b.w};
            #pragma unroll
            for (int c = 0; c < 4; c++) {
                hh.h[c] = __float2bfloat16(bv[c]);
                ll.h[c] = __float2bfloat16(bv[c] - __bfloat162float(hh.h[c]));
            }
            *(uint2*)(sm + GSM_BH + off) = hh.u;
            *(uint2*)(sm + GSM_BL + off) = ll.u;
        }
        __syncthreads();

        // ---- 4 k16-steps of mma ----
        #pragma unroll
        for (int ks = 0; ks < 4; ks++) {
            const uint32_t unit = ks * 2 + (sel >> 1);
            uint32_t ah[2][4], al[2][4];
            #pragma unroll
            for (int mt = 0; mt < 2; mt++) {
                uint32_t rowA = wm + mt * 16 + ((sel & 1) << 3) + l7;
                uint32_t off  = rowA * 128 + ((unit ^ (rowA & 7)) << 4);
                LDSM_X4(ah[mt][0], ah[mt][1], ah[mt][2], ah[mt][3], sb + GSM_AH + off);
                LDSM_X4(al[mt][0], al[mt][1], al[mt][2], al[mt][3], sb + GSM_AL + off);
            }
            #pragma unroll
            for (int ntp = 0; ntp < 4; ntp++) {
                uint32_t rowB = wn + ntp * 16 + ((sel & 1) << 3) + l7;
                uint32_t off  = rowB * 128 + ((unit ^ (rowB & 7)) << 4);
                uint32_t bh0, bh1, bh2, bh3, bl0, bl1, bl2, bl3;
                LDSM_X4(bh0, bh1, bh2, bh3, sb + GSM_BH + off);
                LDSM_X4(bl0, bl1, bl2, bl3, sb + GSM_BL + off);
                #pragma unroll
                for (int mt = 0; mt < 2; mt++) {
                    MMA_BF16(cacc[mt][2 * ntp],     ah[mt], bh0, bh2);
                    MMA_BF16(cacc[mt][2 * ntp],     ah[mt], bl0, bl2);
                    MMA_BF16(cacc[mt][2 * ntp],     al[mt], bh0, bh2);
                    MMA_BF16(cacc[mt][2 * ntp + 1], ah[mt], bh1, bh3);
                    MMA_BF16(cacc[mt][2 * ntp + 1], ah[mt], bl1, bl3);
                    MMA_BF16(cacc[mt][2 * ntp + 1], al[mt], bh1, bh3);
                }
            }
        }
        __syncthreads();
    }

    // ---- epilogue: write C + bias ----
    #pragma unroll
    for (int mt = 0; mt < 2; mt++) {
        int row = m0 + wm + mt * 16 + (lane >> 2);
        #pragma unroll
        for (int nt = 0; nt < 8; nt++) {
            int col = n0 + wn + nt * 8 + ((lane & 3) << 1);
            float bx = bias[col], by = bias[col + 1];
            float2 v0 = {cacc[mt][nt][0] + bx, cacc[mt][nt][1] + by};
            float2 v1 = {cacc[mt][nt][2] + bx, cacc[mt][nt][3] + by};
            *(float2*)&C[(size_t)row * N + col]       = v0;
            *(float2*)&C[(size_t)(row + 8) * N + col] = v1;
        }
    }
}

// ---------------------------------------------------------------------------
// Causal flash attention (fp32), GEMM-style tiles, swizzled smem. (R4 version)
// ---------------------------------------------------------------------------
#define PS_LD 68

__global__ __launch_bounds__(256) void attn_kernel(
    const float* __restrict__ Q, const float* __restrict__ Km,
    const float* __restrict__ Vm, float* __restrict__ O)
{
    extern __shared__ float smem[];
    float* Qt = smem;
    float* Kt = Qt + 64 * 64;
    float* Vs = Kt + 64 * 64;
    float* Ps = Vs + 64 * 64;

    const int tid = threadIdx.x;
    const int tx  = tid & 15;
    const int ty  = tid >> 4;
    const int tile = gridDim.x - 1 - blockIdx.x;
    const int h    = blockIdx.y;
    const int b    = blockIdx.z;
    const int base = b * SEQ;
    const float scale = 0.125f;

    #pragma unroll
    for (int it = 0; it < 4; it++) {
        int idx = it * 256 + tid;
        int r   = idx >> 4;
        int d4  = (idx & 15) * 4;
        size_t g = (size_t)(base + tile * 64 + r) * D_MODEL + h * D_K + d4;
        float4 v = *(const float4*)&Q[g];
        float comp[4] = {v.x, v.y, v.z, v.w};
        #pragma unroll
        for (int c = 0; c < 4; c++) {
            int d = d4 + c;
            int cell = d * 16 + ((r >> 2) ^ ((d >> 2) & 15));
            Qt[cell * 4 + (r & 3)] = comp[c];
        }
    }

    float oacc[4][4];
    #pragma unroll
    for (int i = 0; i < 4; i++)
        #pragma unroll
        for (int j = 0; j < 4; j++) oacc[i][j] = 0.f;
    float mrow[4], lrow[4];
    #pragma unroll
    for (int i = 0; i < 4; i++) { mrow[i] = -1e30f; lrow[i] = 0.f; }

    const float4* Qt4 = (const float4*)Qt;
    const float4* Kt4 = (const float4*)Kt;
    const float4* Vs4 = (const float4*)Vs;
    const float4* Ps4 = (const float4*)Ps;

    for (int t = 0; t <= tile; t++) {
        __syncthreads();
        #pragma unroll
        for (int it = 0; it < 4; it++) {
            int idx = it * 256 + tid;
            int j   = idx >> 4;
            int d4  = (idx & 15) * 4;
            size_t g = (size_t)(base + t * 64 + j) * D_MODEL + h * D_K + d4;
            float4 kv = *(const float4*)&Km[g];
            float comp[4] = {kv.x, kv.y, kv.z, kv.w};
            #pragma unroll
            for (int c = 0; c < 4; c++) {
                int d = d4 + c;
                int cell = d * 16 + ((j >> 2) ^ ((d >> 2) & 15));
                Kt[cell * 4 + (j & 3)] = comp[c];
            }
            *(float4*)&Vs[j * 64 + d4] = *(const float4*)&Vm[g];
        }
        __syncthreads();

        float sacc[4][4];
        #pragma unroll
        for (int i = 0; i < 4; i++)
            #pragma unroll
            for (int j = 0; j < 4; j++) sacc[i][j] = 0.f;

        #pragma unroll 8
        for (int d = 0; d < 64; d++) {
            int swz = (d >> 2) & 15;
            float4 qv = Qt4[d * 16 + (ty ^ swz)];
            float4 kv = Kt4[d * 16 + (tx ^ swz)];
            float qi[4] = {qv.x, qv.y, qv.z, qv.w};
            float ki[4] = {kv.x, kv.y, kv.z, kv.w};
            #pragma unroll
            for (int i = 0; i < 4; i++)
                #pragma unroll
                for (int j = 0; j < 4; j++)
                    sacc[i][j] = fmaf(qi[i], ki[j], sacc[i][j]);
        }

        const bool diag = (t == tile);
        #pragma unroll
        for (int i = 0; i < 4; i++) {
            int r = ty * 4 + i;
            #pragma unroll
            for (int j = 0; j < 4; j++) {
                float s = sacc[i][j] * scale;
                if (diag && (tx * 4 + j > r)) s = -1e30f;
                sacc[i][j] = s;
            }
        }

        #pragma unroll
        for (int i = 0; i < 4; i++) {
            float tm = fmaxf(fmaxf(sacc[i][0], sacc[i][1]),
                             fmaxf(sacc[i][2], sacc[i][3]));
            #pragma unroll
            for (int o = 8; o >= 1; o >>= 1)
                tm = fmaxf(tm, __shfl_xor_sync(0xffffffffu, tm, o));
            float mn = fmaxf(mrow[i], tm);
            float c  = __expf(mrow[i] - mn);
            mrow[i] = mn;

            float ls = 0.f;
            #pragma unroll
            for (int j = 0; j < 4; j++) {
                float p = __expf(sacc[i][j] - mn);
                sacc[i][j] = p;
                ls += p;
            }
            #pragma unroll
            for (int o = 8; o >= 1; o >>= 1)
                ls += __shfl_xor_sync(0xffffffffu, ls, o);
            lrow[i] = lrow[i] * c + ls;

            #pragma unroll
            for (int j = 0; j < 4; j++) oacc[i][j] *= c;

            *(float4*)&Ps[(ty * 4 + i) * PS_LD + tx * 4] = *(float4*)&sacc[i][0];
        }
        __syncthreads();

        #pragma unroll 2
        for (int jq = 0; jq < 16; jq++) {
            float4 p4[4];
            #pragma unroll
            for (int i = 0; i < 4; i++)
                p4[i] = Ps4[(ty * 4 + i) * 17 + jq];
            #pragma unroll
            for (int jj = 0; jj < 4; jj++) {
                float4 vv = Vs4[(jq * 4 + jj) * 16 + tx];
                float vi[4] = {vv.x, vv.y, vv.z, vv.w};
                float pj[4] = {((float*)&p4[0])[jj], ((float*)&p4[1])[jj],
                               ((float*)&p4[2])[jj], ((float*)&p4[3])[jj]};
                #pragma unroll
                for (int i = 0; i < 4; i++)
                    #pragma unroll
                    for (int cc = 0; cc < 4; cc++)
                        oacc[i][cc] = fmaf(pj[i], vi[cc], oacc[i][cc]);
            }
        }
    }

    #pragma unroll
    for (int i = 0; i < 4; i++) {
        float inv = 1.f / lrow[i];
        int row = base + tile * 64 + ty * 4 + i;
        float4 o;
        o.x = oacc[i][0] * inv;
        o.y = oacc[i][1] * inv;
        o.z = oacc[i][2] * inv;
        o.w = oacc[i][3] * inv;
        *(float4*)&O[(size_t)row * D_MODEL + h * D_K + tx * 4] = o;
    }
}

#define ATTN_SMEM ((64*64*3 + 64*PS_LD) * 4)

// ---------------------------------------------------------------------------
// Launch
// ---------------------------------------------------------------------------
extern "C" void kernel_launch(void* const* d_in, const int* in_sizes, int n_in,
                              void* d_out, int out_size)
{
    const float* queries = (const float*)d_in[0];
    const float* keys    = (const float*)d_in[1];
    // d_in[2] = values (unused by reference)
    const float* Wq = (const float*)d_in[3];
    const float* bq = (const float*)d_in[4];
    const float* Wd = (const float*)d_in[5];
    const float* bd = (const float*)d_in[6];
    const float* Wk = (const float*)d_in[7];
    const float* bk = (const float*)d_in[8];
    const float* Wv = (const float*)d_in[9];
    const float* bv = (const float*)d_in[10];
    const float* Wo = (const float*)d_in[11];
    const float* bo = (const float*)d_in[12];
    float* out = (float*)d_out;

    float *pQ, *pK, *pV, *pLat, *pO;
    float *pWqT, *pWdT, *pWkT, *pWvT, *pWoT;
    cudaGetSymbolAddress((void**)&pQ,   g_Q);
    cudaGetSymbolAddress((void**)&pK,   g_K);
    cudaGetSymbolAddress((void**)&pV,   g_V);
    cudaGetSymbolAddress((void**)&pLat, g_lat);
    cudaGetSymbolAddress((void**)&pO,   g_O);
    cudaGetSymbolAddress((void**)&pWqT, g_WqT);
    cudaGetSymbolAddress((void**)&pWdT, g_WdT);
    cudaGetSymbolAddress((void**)&pWkT, g_WkT);
    cudaGetSymbolAddress((void**)&pWvT, g_WvT);
    cudaGetSymbolAddress((void**)&pWoT, g_WoT);

    cudaFuncSetAttribute(attn_kernel,
                         cudaFuncAttributeMaxDynamicSharedMemorySize, ATTN_SMEM);
    cudaFuncSetAttribute(gemm_mma_kernel,
                         cudaFuncAttributeMaxDynamicSharedMemorySize, GEMM_SMEM);

    dim3 tb(32, 8);
    transpose_kernel<<<dim3(D_MODEL/32, D_MODEL/32), tb>>>(Wq, pWqT, D_MODEL, D_MODEL);
    transpose_kernel<<<dim3(LATENT/32,  D_MODEL/32), tb>>>(Wd, pWdT, D_MODEL, LATENT);
    transpose_kernel<<<dim3(D_MODEL/32, LATENT/32),  tb>>>(Wk, pWkT, LATENT, D_MODEL);
    transpose_kernel<<<dim3(D_MODEL/32, LATENT/32),  tb>>>(Wv, pWvT, LATENT, D_MODEL);
    transpose_kernel<<<dim3(D_MODEL/32, D_MODEL/32), tb>>>(Wo, pWoT, D_MODEL, D_MODEL);

    // 1) latent = keys @ Wd + bd
    gemm_mma_kernel<<<dim3(LATENT/128, ROWS/128), 256, GEMM_SMEM>>>(
        keys, pWdT, bd, pLat, ROWS, LATENT, D_MODEL);
    // 2) Q = queries @ Wq + bq
    gemm_mma_kernel<<<dim3(D_MODEL/128, ROWS/128), 256, GEMM_SMEM>>>(
        queries, pWqT, bq, pQ, ROWS, D_MODEL, D_MODEL);
    // 3) K = latent @ Wk + bk
    gemm_mma_kernel<<<dim3(D_MODEL/128, ROWS/128), 256, GEMM_SMEM>>>(
        pLat, pWkT, bk, pK, ROWS, D_MODEL, LATENT);
    // 4) V = latent @ Wv + bv
    gemm_mma_kernel<<<dim3(D_MODEL/128, ROWS/128), 256, GEMM_SMEM>>>(
        pLat, pWvT, bv, pV, ROWS, D_MODEL, LATENT);
    // 5) causal attention -> g_O
    attn_kernel<<<dim3(SEQ/64, N_HEADS, BATCH), dim3(256), ATTN_SMEM>>>(
        pQ, pK, pV, pO);
    // 6) out = O @ Wo + bo
    gemm_mma_kernel<<<dim3(D_MODEL/128, ROWS/128), 256, GEMM_SMEM>>>(
        pO, pWoT, bo, out, ROWS, D_MODEL, D_MODEL);
}

// round 7
// speedup vs baseline: 2.8664x; 1.6412x over previous
#include <cuda_runtime.h>
#include <cuda_bf16.h>
#include <math.h>
#include <stdint.h>

// Problem constants
#define D_MODEL 1024
#define N_HEADS 16
#define D_K     64
#define LATENT  256
#define BATCH   2
#define SEQ     2048
#define ROWS    (BATCH * SEQ)   // 4096

// ---------------------------------------------------------------------------
// Scratch (device globals)
// ---------------------------------------------------------------------------
__device__ __nv_bfloat16 g_latH[ROWS * LATENT], g_latL[ROWS * LATENT];
__device__ __nv_bfloat16 g_QH[ROWS * D_MODEL], g_QL[ROWS * D_MODEL];
__device__ __nv_bfloat16 g_KH[ROWS * D_MODEL], g_KL[ROWS * D_MODEL];
__device__ __nv_bfloat16 g_VH[ROWS * D_MODEL], g_VL[ROWS * D_MODEL];
__device__ float g_O[ROWS * D_MODEL];
// pre-split transposed weights [N][K] bf16 hi/lo
__device__ __nv_bfloat16 g_WqTH[D_MODEL * D_MODEL], g_WqTL[D_MODEL * D_MODEL];
__device__ __nv_bfloat16 g_WdTH[LATENT * D_MODEL],  g_WdTL[LATENT * D_MODEL];
__device__ __nv_bfloat16 g_WkTH[D_MODEL * LATENT],  g_WkTL[D_MODEL * LATENT];
__device__ __nv_bfloat16 g_WvTH[D_MODEL * LATENT],  g_WvTL[D_MODEL * LATENT];
__device__ __nv_bfloat16 g_WoTH[D_MODEL * D_MODEL], g_WoTL[D_MODEL * D_MODEL];

__device__ __forceinline__ uint32_t smem_u32(const void* p) {
    uint32_t a;
    asm("{ .reg .u64 t; cvta.to.shared.u64 t, %1; cvt.u32.u64 %0, t; }"
        : "=r"(a) : "l"(p));
    return a;
}

#define LDSM_X4(r0, r1, r2, r3, addr) \
    asm volatile("ldmatrix.sync.aligned.m8n8.x4.shared.b16 {%0,%1,%2,%3}, [%4];" \
        : "=r"(r0), "=r"(r1), "=r"(r2), "=r"(r3) : "r"(addr))

#define LDSM_X4_T(r0, r1, r2, r3, addr) \
    asm volatile("ldmatrix.sync.aligned.m8n8.x4.trans.shared.b16 {%0,%1,%2,%3}, [%4];" \
        : "=r"(r0), "=r"(r1), "=r"(r2), "=r"(r3) : "r"(addr))

#define MMA_BF16(c, a, b0v, b1v) \
    asm volatile("mma.sync.aligned.m16n8k16.row.col.f32.bf16.bf16.f32 " \
        "{%0,%1,%2,%3}, {%4,%5,%6,%7}, {%8,%9}, {%0,%1,%2,%3};" \
        : "+f"((c)[0]), "+f"((c)[1]), "+f"((c)[2]), "+f"((c)[3]) \
        : "r"((a)[0]), "r"((a)[1]), "r"((a)[2]), "r"((a)[3]), "r"(b0v), "r"(b1v))

// Fast exp on FMA/ALU pipes (no MUFU). Valid for x <= 0 (clamped at -80).
__device__ __forceinline__ float fexp(float x) {
    x = fmaxf(x, -80.f);
    float t2 = x * 1.4426950408889634f;
    float r  = t2 + 12582912.f;                    // round-to-nearest int
    int   n  = __float_as_int(r) - 0x4B400000;
    float f  = t2 - (r - 12582912.f);              // f in [-0.5, 0.5]
    float p  = fmaf(f, 0.0096181291f, 0.0555041087f);
    p = fmaf(f, p, 0.2402265069f);
    p = fmaf(f, p, 0.6931471806f);
    p = fmaf(f, p, 1.0f);
    return p * __int_as_float((127 + n) << 23);
}

__device__ __forceinline__ uint32_t pack_bf2(float a, float b) {
    __nv_bfloat162 t = __floats2bfloat162_rn(a, b);
    return *(uint32_t*)&t;
}

// ---------------------------------------------------------------------------
// Weight transpose + split: WtH/WtL[n][k] = split(W[k][n])
// ---------------------------------------------------------------------------
__global__ void transpose_split_kernel(const float* __restrict__ W,
                                       __nv_bfloat16* __restrict__ WtH,
                                       __nv_bfloat16* __restrict__ WtL,
                                       int K, int N)
{
    __shared__ float t[32][33];
    int kb = blockIdx.y * 32, nb = blockIdx.x * 32;
    int x = threadIdx.x, y = threadIdx.y;   // 32 x 8
    #pragma unroll
    for (int i = 0; i < 32; i += 8)
        t[y + i][x] = W[(size_t)(kb + y + i) * N + nb + x];
    __syncthreads();
    #pragma unroll
    for (int i = 0; i < 32; i += 8) {
        float v = t[x][y + i];
        __nv_bfloat16 h = __float2bfloat16(v);
        WtH[(size_t)(nb + y + i) * K + kb + x] = h;
        WtL[(size_t)(nb + y + i) * K + kb + x] =
            __float2bfloat16(v - __bfloat162float(h));
    }
}

// ---------------------------------------------------------------------------
// Split-bf16 tensor-core GEMM. C = A @ BT^T + bias, scaled.
// ASPLIT: A given as bf16 hi/lo arrays, else fp32 (split in loader).
// OSPLIT: output written as bf16 hi/lo, else fp32.
// 128x128 CTA, BK=64, 256 threads (8 warps, 32x64 warp tile).
// ---------------------------------------------------------------------------
#define GSM_AH 0
#define GSM_AL 16384
#define GSM_BH 32768
#define GSM_BL 49152
#define GEMM_SMEM 65536

template<bool ASPLIT, bool OSPLIT>
__global__ __launch_bounds__(256) void gemm_mma(
    const float* __restrict__ Af,
    const __nv_bfloat16* __restrict__ AHg, const __nv_bfloat16* __restrict__ ALg,
    const __nv_bfloat16* __restrict__ BHg, const __nv_bfloat16* __restrict__ BLg,
    const float* __restrict__ bias, float scale,
    float* __restrict__ Cf,
    __nv_bfloat16* __restrict__ CHg, __nv_bfloat16* __restrict__ CLg,
    int M, int N, int K)
{
    extern __shared__ char sm[];
    const uint32_t sb = smem_u32(sm);
    const int tid  = threadIdx.x;
    const int lane = tid & 31;
    const int wid  = tid >> 5;
    const int wm   = (wid & 3) * 32;
    const int wn   = (wid >> 2) * 64;
    const int m0   = blockIdx.y * 128;
    const int n0   = blockIdx.x * 128;
    const int sel  = lane >> 3;
    const int l7   = lane & 7;

    float cacc[2][8][4];
    #pragma unroll
    for (int mt = 0; mt < 2; mt++)
        #pragma unroll
        for (int nt = 0; nt < 8; nt++)
            #pragma unroll
            for (int i = 0; i < 4; i++) cacc[mt][nt][i] = 0.f;

    for (int k0 = 0; k0 < K; k0 += 64) {
        // ---- A tile ----
        if (ASPLIT) {
            #pragma unroll
            for (int it = 0; it < 4; it++) {
                int idx = it * 256 + tid;        // 1024 uint4 slots
                int row = idx >> 3, c8 = (idx & 7) << 3;
                uint32_t off = row * 128 + ((((c8 >> 3) ^ (row & 7))) << 4);
                size_t g = (size_t)(m0 + row) * K + k0 + c8;
                *(uint4*)(sm + GSM_AH + off) = *(const uint4*)&AHg[g];
                *(uint4*)(sm + GSM_AL + off) = *(const uint4*)&ALg[g];
            }
        } else {
            #pragma unroll
            for (int it = 0; it < 8; it++) {
                int idx = it * 256 + tid;        // 2048 float4 slots
                int row = idx >> 4, c4 = (idx & 15) << 2;
                float4 a = *(const float4*)&Af[(size_t)(m0 + row) * K + k0 + c4];
                uint32_t off = row * 128 + ((((c4 >> 3) ^ (row & 7))) << 4)
                             + ((c4 & 7) << 1);
                union { __nv_bfloat16 h[4]; uint2 u; } hh, ll;
                float av[4] = {a.x, a.y, a.z, a.w};
                #pragma unroll
                for (int c = 0; c < 4; c++) {
                    hh.h[c] = __float2bfloat16(av[c]);
                    ll.h[c] = __float2bfloat16(av[c] - __bfloat162float(hh.h[c]));
                }
                *(uint2*)(sm + GSM_AH + off) = hh.u;
                *(uint2*)(sm + GSM_AL + off) = ll.u;
            }
        }
        // ---- B tile (always pre-split bf16) ----
        #pragma unroll
        for (int it = 0; it < 4; it++) {
            int idx = it * 256 + tid;
            int row = idx >> 3, c8 = (idx & 7) << 3;
            uint32_t off = row * 128 + ((((c8 >> 3) ^ (row & 7))) << 4);
            size_t g = (size_t)(n0 + row) * K + k0 + c8;
            *(uint4*)(sm + GSM_BH + off) = *(const uint4*)&BHg[g];
            *(uint4*)(sm + GSM_BL + off) = *(const uint4*)&BLg[g];
        }
        __syncthreads();

        #pragma unroll
        for (int ks = 0; ks < 4; ks++) {
            const uint32_t unit = ks * 2 + (sel >> 1);
            uint32_t ah[2][4], al[2][4];
            #pragma unroll
            for (int mt = 0; mt < 2; mt++) {
                uint32_t rowA = wm + mt * 16 + ((sel & 1) << 3) + l7;
                uint32_t off  = rowA * 128 + ((unit ^ (rowA & 7)) << 4);
                LDSM_X4(ah[mt][0], ah[mt][1], ah[mt][2], ah[mt][3], sb + GSM_AH + off);
                LDSM_X4(al[mt][0], al[mt][1], al[mt][2], al[mt][3], sb + GSM_AL + off);
            }
            #pragma unroll
            for (int ntp = 0; ntp < 4; ntp++) {
                uint32_t rowB = wn + ntp * 16 + ((sel & 1) << 3) + l7;
                uint32_t off  = rowB * 128 + ((unit ^ (rowB & 7)) << 4);
                uint32_t bh0, bh1, bh2, bh3, bl0, bl1, bl2, bl3;
                LDSM_X4(bh0, bh1, bh2, bh3, sb + GSM_BH + off);
                LDSM_X4(bl0, bl1, bl2, bl3, sb + GSM_BL + off);
                #pragma unroll
                for (int mt = 0; mt < 2; mt++) {
                    MMA_BF16(cacc[mt][2 * ntp],     ah[mt], bh0, bh2);
                    MMA_BF16(cacc[mt][2 * ntp],     ah[mt], bl0, bl2);
                    MMA_BF16(cacc[mt][2 * ntp],     al[mt], bh0, bh2);
                    MMA_BF16(cacc[mt][2 * ntp + 1], ah[mt], bh1, bh3);
                    MMA_BF16(cacc[mt][2 * ntp + 1], ah[mt], bl1, bl3);
                    MMA_BF16(cacc[mt][2 * ntp + 1], al[mt], bh1, bh3);
                }
            }
        }
        __syncthreads();
    }

    // ---- epilogue ----
    #pragma unroll
    for (int mt = 0; mt < 2; mt++) {
        int row = m0 + wm + mt * 16 + (lane >> 2);
        #pragma unroll
        for (int nt = 0; nt < 8; nt++) {
            int col = n0 + wn + nt * 8 + ((lane & 3) << 1);
            float bx = bias[col], by = bias[col + 1];
            float v0 = (cacc[mt][nt][0] + bx) * scale;
            float v1 = (cacc[mt][nt][1] + by) * scale;
            float v2 = (cacc[mt][nt][2] + bx) * scale;
            float v3 = (cacc[mt][nt][3] + by) * scale;
            if (OSPLIT) {
                __nv_bfloat162 h01 = __floats2bfloat162_rn(v0, v1);
                __nv_bfloat162 h23 = __floats2bfloat162_rn(v2, v3);
                __nv_bfloat162 l01 = __floats2bfloat162_rn(
                    v0 - __bfloat162float(h01.x), v1 - __bfloat162float(h01.y));
                __nv_bfloat162 l23 = __floats2bfloat162_rn(
                    v2 - __bfloat162float(h23.x), v3 - __bfloat162float(h23.y));
                *(__nv_bfloat162*)&CHg[(size_t)row * N + col]       = h01;
                *(__nv_bfloat162*)&CHg[(size_t)(row + 8) * N + col] = h23;
                *(__nv_bfloat162*)&CLg[(size_t)row * N + col]       = l01;
                *(__nv_bfloat162*)&CLg[(size_t)(row + 8) * N + col] = l23;
            } else {
                float2 a = {v0, v1}, b = {v2, v3};
                *(float2*)&Cf[(size_t)row * N + col]       = a;
                *(float2*)&Cf[(size_t)(row + 8) * N + col] = b;
            }
        }
    }
}

// ---------------------------------------------------------------------------
// Flash attention, split-bf16 mma.sync, poly-exp softmax.
// 128 threads (4 warps), 64-query tile; each warp owns 16 q-rows.
// Scale 0.125 pre-folded into Q. QK and PV each 3-term split HMMA.
// ---------------------------------------------------------------------------
__global__ __launch_bounds__(128) void attn_mma_kernel(
    const __nv_bfloat16* __restrict__ QHg, const __nv_bfloat16* __restrict__ QLg,
    const __nv_bfloat16* __restrict__ KHg, const __nv_bfloat16* __restrict__ KLg,
    const __nv_bfloat16* __restrict__ VHg, const __nv_bfloat16* __restrict__ VLg,
    float* __restrict__ O)
{
    __shared__ __align__(16) char sKH[8192];
    __shared__ __align__(16) char sKL[8192];
    __shared__ __align__(16) char sVH[8192];
    __shared__ __align__(16) char sVL[8192];
    const uint32_t bKH = smem_u32(sKH), bKL = smem_u32(sKL);
    const uint32_t bVH = smem_u32(sVH), bVL = smem_u32(sVL);

    const int tid  = threadIdx.x;
    const int lane = tid & 31;
    const int warp = tid >> 5;
    const int tile = gridDim.x - 1 - blockIdx.x;  // longest first
    const int h    = blockIdx.y;
    const int b    = blockIdx.z;
    const int base = b * SEQ;
    const int sel  = lane >> 3;
    const int l7   = lane & 7;
    const int wq   = warp * 16;

    // ---- stage Q tile into sKH/sKL, extract A-frags ----
    #pragma unroll
    for (int it = 0; it < 4; it++) {
        int idx = it * 128 + tid;
        int r = idx >> 3, c8 = (idx & 7) << 3;
        size_t g = (size_t)(base + tile * 64 + r) * D_MODEL + h * D_K + c8;
        uint32_t off = r * 128 + ((((c8 >> 3) ^ (r & 7))) << 4);
        *(uint4*)(sKH + off) = *(const uint4*)&QHg[g];
        *(uint4*)(sKL + off) = *(const uint4*)&QLg[g];
    }
    __syncthreads();
    uint32_t qh[4][4], ql[4][4];
    #pragma unroll
    for (int kc = 0; kc < 4; kc++) {
        uint32_t row = wq + ((sel & 1) << 3) + l7;
        uint32_t off = row * 128 + ((((uint32_t)(kc * 2 + (sel >> 1)) ^ (row & 7))) << 4);
        LDSM_X4(qh[kc][0], qh[kc][1], qh[kc][2], qh[kc][3], bKH + off);
        LDSM_X4(ql[kc][0], ql[kc][1], ql[kc][2], ql[kc][3], bKL + off);
    }
    __syncthreads();

    float oacc[8][4];
    #pragma unroll
    for (int ng = 0; ng < 8; ng++)
        #pragma unroll
        for (int i = 0; i < 4; i++) oacc[ng][i] = 0.f;
    float mrow[2] = {-1e30f, -1e30f};
    float lrow[2] = {0.f, 0.f};

    for (int t = 0; t <= tile; t++) {
        // ---- load K/V hi/lo tiles ----
        #pragma unroll
        for (int it = 0; it < 4; it++) {
            int idx = it * 128 + tid;
            int j = idx >> 3, c8 = (idx & 7) << 3;
            size_t g = (size_t)(base + t * 64 + j) * D_MODEL + h * D_K + c8;
            uint32_t off = j * 128 + ((((c8 >> 3) ^ (j & 7))) << 4);
            *(uint4*)(sKH + off) = *(const uint4*)&KHg[g];
            *(uint4*)(sKL + off) = *(const uint4*)&KLg[g];
            *(uint4*)(sVH + off) = *(const uint4*)&VHg[g];
            *(uint4*)(sVL + off) = *(const uint4*)&VLg[g];
        }
        __syncthreads();

        // ---- S = Q @ K^T ----
        float sacc[8][4];
        #pragma unroll
        for (int nt = 0; nt < 8; nt++)
            #pragma unroll
            for (int i = 0; i < 4; i++) sacc[nt][i] = 0.f;

        #pragma unroll
        for (int kc = 0; kc < 4; kc++) {
            const uint32_t unit = kc * 2 + (sel >> 1);
            #pragma unroll
            for (int ntp = 0; ntp < 4; ntp++) {
                uint32_t rowB = ntp * 16 + ((sel & 1) << 3) + l7;
                uint32_t off  = rowB * 128 + ((unit ^ (rowB & 7)) << 4);
                uint32_t bh0, bh1, bh2, bh3, bl0, bl1, bl2, bl3;
                LDSM_X4(bh0, bh1, bh2, bh3, bKH + off);
                LDSM_X4(bl0, bl1, bl2, bl3, bKL + off);
                MMA_BF16(sacc[2 * ntp],     qh[kc], bh0, bh2);
                MMA_BF16(sacc[2 * ntp],     qh[kc], bl0, bl2);
                MMA_BF16(sacc[2 * ntp],     ql[kc], bh0, bh2);
                MMA_BF16(sacc[2 * ntp + 1], qh[kc], bh1, bh3);
                MMA_BF16(sacc[2 * ntp + 1], qh[kc], bl1, bl3);
                MMA_BF16(sacc[2 * ntp + 1], ql[kc], bh1, bh3);
            }
        }

        // ---- causal mask on diagonal tile ----
        if (t == tile) {
            int r0 = wq + (lane >> 2);
            #pragma unroll
            for (int nt = 0; nt < 8; nt++) {
                int cb = nt * 8 + ((lane & 3) << 1);
                if (cb     > r0)     sacc[nt][0] = -1e30f;
                if (cb + 1 > r0)     sacc[nt][1] = -1e30f;
                if (cb     > r0 + 8) sacc[nt][2] = -1e30f;
                if (cb + 1 > r0 + 8) sacc[nt][3] = -1e30f;
            }
        }

        // ---- online softmax (per warp; rows fully owned) ----
        #pragma unroll
        for (int ri = 0; ri < 2; ri++) {
            const int e0 = ri * 2, e1 = ri * 2 + 1;
            float rm = -1e30f;
            #pragma unroll
            for (int nt = 0; nt < 8; nt++)
                rm = fmaxf(rm, fmaxf(sacc[nt][e0], sacc[nt][e1]));
            rm = fmaxf(rm, __shfl_xor_sync(0xffffffffu, rm, 1));
            rm = fmaxf(rm, __shfl_xor_sync(0xffffffffu, rm, 2));
            float mn = fmaxf(mrow[ri], rm);
            float corr = fexp(mrow[ri] - mn);
            mrow[ri] = mn;
            lrow[ri] *= corr;
            #pragma unroll
            for (int ng = 0; ng < 8; ng++) {
                oacc[ng][e0] *= corr;
                oacc[ng][e1] *= corr;
            }
            float ls = 0.f;
            #pragma unroll
            for (int nt = 0; nt < 8; nt++) {
                float p0 = fexp(sacc[nt][e0] - mn);
                float p1 = fexp(sacc[nt][e1] - mn);
                sacc[nt][e0] = p0;
                sacc[nt][e1] = p1;
                ls += p0 + p1;
            }
            lrow[ri] += ls;
        }

        // ---- O += P @ V ----
        #pragma unroll
        for (int kc = 0; kc < 4; kc++) {
            uint32_t aH[4], aL[4];
            {
                float c0 = sacc[2 * kc][0],     c1 = sacc[2 * kc][1];
                float c2 = sacc[2 * kc][2],     c3 = sacc[2 * kc][3];
                float d0 = sacc[2 * kc + 1][0], d1 = sacc[2 * kc + 1][1];
                float d2 = sacc[2 * kc + 1][2], d3 = sacc[2 * kc + 1][3];
                aH[0] = pack_bf2(c0, c1);
                aH[1] = pack_bf2(c2, c3);
                aH[2] = pack_bf2(d0, d1);
                aH[3] = pack_bf2(d2, d3);
                __nv_bfloat162 h0 = *(__nv_bfloat162*)&aH[0];
                __nv_bfloat162 h1 = *(__nv_bfloat162*)&aH[1];
                __nv_bfloat162 h2 = *(__nv_bfloat162*)&aH[2];
                __nv_bfloat162 h3 = *(__nv_bfloat162*)&aH[3];
                aL[0] = pack_bf2(c0 - __bfloat162float(h0.x), c1 - __bfloat162float(h0.y));
                aL[1] = pack_bf2(c2 - __bfloat162float(h1.x), c3 - __bfloat162float(h1.y));
                aL[2] = pack_bf2(d0 - __bfloat162float(h2.x), d1 - __bfloat162float(h2.y));
                aL[3] = pack_bf2(d2 - __bfloat162float(h3.x), d3 - __bfloat162float(h3.y));
            }
            #pragma unroll
            for (int dp = 0; dp < 4; dp++) {
                uint32_t rowV = kc * 16 + ((sel & 1) << 3) + l7;
                uint32_t unit = dp * 2 + (sel >> 1);
                uint32_t off  = rowV * 128 + ((unit ^ (rowV & 7)) << 4);
                uint32_t vh0, vh1, vh2, vh3, vl0, vl1, vl2, vl3;
                LDSM_X4_T(vh0, vh1, vh2, vh3, bVH + off);
                LDSM_X4_T(vl0, vl1, vl2, vl3, bVL + off);
                MMA_BF16(oacc[2 * dp],     aH, vh0, vh1);
                MMA_BF16(oacc[2 * dp],     aH, vl0, vl1);
                MMA_BF16(oacc[2 * dp],     aL, vh0, vh1);
                MMA_BF16(oacc[2 * dp + 1], aH, vh2, vh3);
                MMA_BF16(oacc[2 * dp + 1], aH, vl2, vl3);
                MMA_BF16(oacc[2 * dp + 1], aL, vh2, vh3);
            }
        }
        __syncthreads();
    }

    // ---- finalize ----
    #pragma unroll
    for (int ri = 0; ri < 2; ri++) {
        lrow[ri] += __shfl_xor_sync(0xffffffffu, lrow[ri], 1);
        lrow[ri] += __shfl_xor_sync(0xffffffffu, lrow[ri], 2);
    }
    float inv0 = 1.f / lrow[0], inv1 = 1.f / lrow[1];
    int row0 = base + tile * 64 + wq + (lane >> 2);
    #pragma unroll
    for (int ng = 0; ng < 8; ng++) {
        int col = h * D_K + ng * 8 + ((lane & 3) << 1);
        float2 a = {oacc[ng][0] * inv0, oacc[ng][1] * inv0};
        float2 b2 = {oacc[ng][2] * inv1, oacc[ng][3] * inv1};
        *(float2*)&O[(size_t)row0 * D_MODEL + col]       = a;
        *(float2*)&O[(size_t)(row0 + 8) * D_MODEL + col] = b2;
    }
}

// ---------------------------------------------------------------------------
// Launch
// ---------------------------------------------------------------------------
extern "C" void kernel_launch(void* const* d_in, const int* in_sizes, int n_in,
                              void* d_out, int out_size)
{
    const float* queries = (const float*)d_in[0];
    const float* keys    = (const float*)d_in[1];
    // d_in[2] = values (unused by reference)
    const float* Wq = (const float*)d_in[3];
    const float* bq = (const float*)d_in[4];
    const float* Wd = (const float*)d_in[5];
    const float* bd = (const float*)d_in[6];
    const float* Wk = (const float*)d_in[7];
    const float* bk = (const float*)d_in[8];
    const float* Wv = (const float*)d_in[9];
    const float* bv = (const float*)d_in[10];
    const float* Wo = (const float*)d_in[11];
    const float* bo = (const float*)d_in[12];
    float* out = (float*)d_out;

    __nv_bfloat16 *pLatH, *pLatL, *pQH, *pQL, *pKH, *pKL, *pVH, *pVL;
    __nv_bfloat16 *pWqTH, *pWqTL, *pWdTH, *pWdTL, *pWkTH, *pWkTL, *pWvTH, *pWvTL, *pWoTH, *pWoTL;
    float* pO;
    cudaGetSymbolAddress((void**)&pLatH, g_latH);
    cudaGetSymbolAddress((void**)&pLatL, g_latL);
    cudaGetSymbolAddress((void**)&pQH, g_QH);
    cudaGetSymbolAddress((void**)&pQL, g_QL);
    cudaGetSymbolAddress((void**)&pKH, g_KH);
    cudaGetSymbolAddress((void**)&pKL, g_KL);
    cudaGetSymbolAddress((void**)&pVH, g_VH);
    cudaGetSymbolAddress((void**)&pVL, g_VL);
    cudaGetSymbolAddress((void**)&pO,  g_O);
    cudaGetSymbolAddress((void**)&pWqTH, g_WqTH);
    cudaGetSymbolAddress((void**)&pWqTL, g_WqTL);
    cudaGetSymbolAddress((void**)&pWdTH, g_WdTH);
    cudaGetSymbolAddress((void**)&pWdTL, g_WdTL);
    cudaGetSymbolAddress((void**)&pWkTH, g_WkTH);
    cudaGetSymbolAddress((void**)&pWkTL, g_WkTL);
    cudaGetSymbolAddress((void**)&pWvTH, g_WvTH);
    cudaGetSymbolAddress((void**)&pWvTL, g_WvTL);
    cudaGetSymbolAddress((void**)&pWoTH, g_WoTH);
    cudaGetSymbolAddress((void**)&pWoTL, g_WoTL);

    cudaFuncSetAttribute(gemm_mma<false, true>,
                         cudaFuncAttributeMaxDynamicSharedMemorySize, GEMM_SMEM);
    cudaFuncSetAttribute(gemm_mma<true, true>,
                         cudaFuncAttributeMaxDynamicSharedMemorySize, GEMM_SMEM);
    cudaFuncSetAttribute(gemm_mma<false, false>,
                         cudaFuncAttributeMaxDynamicSharedMemorySize, GEMM_SMEM);

    dim3 tb(32, 8);
    transpose_split_kernel<<<dim3(D_MODEL/32, D_MODEL/32), tb>>>(Wq, pWqTH, pWqTL, D_MODEL, D_MODEL);
    transpose_split_kernel<<<dim3(LATENT/32,  D_MODEL/32), tb>>>(Wd, pWdTH, pWdTL, D_MODEL, LATENT);
    transpose_split_kernel<<<dim3(D_MODEL/32, LATENT/32),  tb>>>(Wk, pWkTH, pWkTL, LATENT, D_MODEL);
    transpose_split_kernel<<<dim3(D_MODEL/32, LATENT/32),  tb>>>(Wv, pWvTH, pWvTL, LATENT, D_MODEL);
    transpose_split_kernel<<<dim3(D_MODEL/32, D_MODEL/32), tb>>>(Wo, pWoTH, pWoTL, D_MODEL, D_MODEL);

    // 1) latent = keys @ Wd + bd  (fp32 in, split out)
    gemm_mma<false, true><<<dim3(LATENT/128, ROWS/128), 256, GEMM_SMEM>>>(
        keys, nullptr, nullptr, pWdTH, pWdTL, bd, 1.f,
        nullptr, pLatH, pLatL, ROWS, LATENT, D_MODEL);
    // 2) Q = (queries @ Wq + bq) * 0.125  (fp32 in, split out)
    gemm_mma<false, true><<<dim3(D_MODEL/128, ROWS/128), 256, GEMM_SMEM>>>(
        queries, nullptr, nullptr, pWqTH, pWqTL, bq, 0.125f,
        nullptr, pQH, pQL, ROWS, D_MODEL, D_MODEL);
    // 3) K = latent @ Wk + bk  (split in, split out)
    gemm_mma<true, true><<<dim3(D_MODEL/128, ROWS/128), 256, GEMM_SMEM>>>(
        nullptr, pLatH, pLatL, pWkTH, pWkTL, bk, 1.f,
        nullptr, pKH, pKL, ROWS, D_MODEL, LATENT);
    // 4) V = latent @ Wv + bv  (split in, split out)
    gemm_mma<true, true><<<dim3(D_MODEL/128, ROWS/128), 256, GEMM_SMEM>>>(
        nullptr, pLatH, pLatL, pWvTH, pWvTL, bv, 1.f,
        nullptr, pVH, pVL, ROWS, D_MODEL, LATENT);
    // 5) attention
    attn_mma_kernel<<<dim3(SEQ/64, N_HEADS, BATCH), 128>>>(
        pQH, pQL, pKH, pKL, pVH, pVL, pO);
    // 6) out = O @ Wo + bo  (fp32 in, fp32 out)
    gemm_mma<false, false><<<dim3(D_MODEL/128, ROWS/128), 256, GEMM_SMEM>>>(
        pO, nullptr, nullptr, pWoTH, pWoTL, bo, 1.f,
        out, nullptr, nullptr, ROWS, D_MODEL, D_MODEL);
}

// round 8
// speedup vs baseline: 3.4566x; 1.2059x over previous
#include <cuda_runtime.h>
#include <cuda_bf16.h>
#include <math.h>
#include <stdint.h>

// Problem constants
#define D_MODEL 1024
#define N_HEADS 16
#define D_K     64
#define LATENT  256
#define BATCH   2
#define SEQ     2048
#define ROWS    (BATCH * SEQ)   // 4096

// ---------------------------------------------------------------------------
// Scratch (device globals)
// ---------------------------------------------------------------------------
__device__ __nv_bfloat16 g_qinH[ROWS * D_MODEL], g_qinL[ROWS * D_MODEL];
__device__ __nv_bfloat16 g_kinH[ROWS * D_MODEL], g_kinL[ROWS * D_MODEL];
__device__ __nv_bfloat16 g_latH[ROWS * LATENT], g_latL[ROWS * LATENT];
__device__ __nv_bfloat16 g_QH[ROWS * D_MODEL], g_QL[ROWS * D_MODEL];
__device__ __nv_bfloat16 g_KH[ROWS * D_MODEL], g_KL[ROWS * D_MODEL];
__device__ __nv_bfloat16 g_VH[ROWS * D_MODEL], g_VL[ROWS * D_MODEL];
__device__ __nv_bfloat16 g_OH[ROWS * D_MODEL], g_OL[ROWS * D_MODEL];
// pre-split transposed weights [N][K] bf16 hi/lo
__device__ __nv_bfloat16 g_WqTH[D_MODEL * D_MODEL], g_WqTL[D_MODEL * D_MODEL];
__device__ __nv_bfloat16 g_WdTH[LATENT * D_MODEL],  g_WdTL[LATENT * D_MODEL];
__device__ __nv_bfloat16 g_WkTH[D_MODEL * LATENT],  g_WkTL[D_MODEL * LATENT];
__device__ __nv_bfloat16 g_WvTH[D_MODEL * LATENT],  g_WvTL[D_MODEL * LATENT];
__device__ __nv_bfloat16 g_WoTH[D_MODEL * D_MODEL], g_WoTL[D_MODEL * D_MODEL];

__device__ __forceinline__ uint32_t smem_u32(const void* p) {
    uint32_t a;
    asm("{ .reg .u64 t; cvta.to.shared.u64 t, %1; cvt.u32.u64 %0, t; }"
        : "=r"(a) : "l"(p));
    return a;
}

#define LDSM_X4(r0, r1, r2, r3, addr) \
    asm volatile("ldmatrix.sync.aligned.m8n8.x4.shared.b16 {%0,%1,%2,%3}, [%4];" \
        : "=r"(r0), "=r"(r1), "=r"(r2), "=r"(r3) : "r"(addr))

#define LDSM_X4_T(r0, r1, r2, r3, addr) \
    asm volatile("ldmatrix.sync.aligned.m8n8.x4.trans.shared.b16 {%0,%1,%2,%3}, [%4];" \
        : "=r"(r0), "=r"(r1), "=r"(r2), "=r"(r3) : "r"(addr))

#define MMA_BF16(c, a, b0v, b1v) \
    asm volatile("mma.sync.aligned.m16n8k16.row.col.f32.bf16.bf16.f32 " \
        "{%0,%1,%2,%3}, {%4,%5,%6,%7}, {%8,%9}, {%0,%1,%2,%3};" \
        : "+f"((c)[0]), "+f"((c)[1]), "+f"((c)[2]), "+f"((c)[3]) \
        : "r"((a)[0]), "r"((a)[1]), "r"((a)[2]), "r"((a)[3]), "r"(b0v), "r"(b1v))

#define CP16(dst, src) \
    asm volatile("cp.async.cg.shared.global [%0], [%1], 16;" \
        :: "r"(dst), "l"(src) : "memory")
#define CP_COMMIT() asm volatile("cp.async.commit_group;" ::: "memory")
#define CP_WAIT(n)  asm volatile("cp.async.wait_group %0;" :: "n"(n) : "memory")

// Fast exp on FMA/ALU pipes (no MUFU). Valid for x <= 0 (clamped at -80).
__device__ __forceinline__ float fexp(float x) {
    x = fmaxf(x, -80.f);
    float t2 = x * 1.4426950408889634f;
    float r  = t2 + 12582912.f;
    int   n  = __float_as_int(r) - 0x4B400000;
    float f  = t2 - (r - 12582912.f);
    float p  = fmaf(f, 0.0096181291f, 0.0555041087f);
    p = fmaf(f, p, 0.2402265069f);
    p = fmaf(f, p, 0.6931471806f);
    p = fmaf(f, p, 1.0f);
    return p * __int_as_float((127 + n) << 23);
}

__device__ __forceinline__ uint32_t pack_bf2(float a, float b) {
    __nv_bfloat162 t = __floats2bfloat162_rn(a, b);
    return *(uint32_t*)&t;
}

// ---------------------------------------------------------------------------
// Elementwise fp32 -> bf16 hi/lo split
// ---------------------------------------------------------------------------
__global__ void split_kernel(const float* __restrict__ X,
                             __nv_bfloat16* __restrict__ H,
                             __nv_bfloat16* __restrict__ L, int n4)
{
    int idx = blockIdx.x * blockDim.x + threadIdx.x;
    int stride = gridDim.x * blockDim.x;
    for (; idx < n4; idx += stride) {
        float4 v = ((const float4*)X)[idx];
        float a[4] = {v.x, v.y, v.z, v.w};
        union { __nv_bfloat16 b[4]; uint2 u; } hh, ll;
        #pragma unroll
        for (int c = 0; c < 4; c++) {
            hh.b[c] = __float2bfloat16(a[c]);
            ll.b[c] = __float2bfloat16(a[c] - __bfloat162float(hh.b[c]));
        }
        ((uint2*)H)[idx] = hh.u;
        ((uint2*)L)[idx] = ll.u;
    }
}

// ---------------------------------------------------------------------------
// Weight transpose + split: WtH/WtL[n][k] = split(W[k][n])
// ---------------------------------------------------------------------------
__global__ void transpose_split_kernel(const float* __restrict__ W,
                                       __nv_bfloat16* __restrict__ WtH,
                                       __nv_bfloat16* __restrict__ WtL,
                                       int K, int N)
{
    __shared__ float t[32][33];
    int kb = blockIdx.y * 32, nb = blockIdx.x * 32;
    int x = threadIdx.x, y = threadIdx.y;   // 32 x 8
    #pragma unroll
    for (int i = 0; i < 32; i += 8)
        t[y + i][x] = W[(size_t)(kb + y + i) * N + nb + x];
    __syncthreads();
    #pragma unroll
    for (int i = 0; i < 32; i += 8) {
        float v = t[x][y + i];
        __nv_bfloat16 h = __float2bfloat16(v);
        WtH[(size_t)(nb + y + i) * K + kb + x] = h;
        WtL[(size_t)(nb + y + i) * K + kb + x] =
            __float2bfloat16(v - __bfloat162float(h));
    }
}

// ---------------------------------------------------------------------------
// Split-bf16 tensor-core GEMM, cp.async double-buffered.
// C = A @ BT^T + bias (scaled). All operands pre-split bf16 hi/lo.
// 128x128 CTA, BK=64, 256 threads (8 warps, 32x64 warp tile), 2 stages.
// ---------------------------------------------------------------------------
#define STG 65536            // bytes per stage (AH/AL/BH/BL x 16KB)
#define OFF_AH 0
#define OFF_AL 16384
#define OFF_BH 32768
#define OFF_BL 49152
#define GEMM_SMEM (2 * STG)

__device__ __forceinline__ void gemm_prefetch(
    uint32_t sb, int stage, int tid, int m0, int n0, int k0, int K,
    const __nv_bfloat16* AHg, const __nv_bfloat16* ALg,
    const __nv_bfloat16* BHg, const __nv_bfloat16* BLg)
{
    const uint32_t base = sb + stage * STG;
    #pragma unroll
    for (int it = 0; it < 4; it++) {
        int idx = it * 256 + tid;            // 1024 16B chunks per array
        int row = idx >> 3, c8 = (idx & 7) << 3;
        uint32_t off = row * 128 + ((((c8 >> 3) ^ (row & 7))) << 4);
        size_t ga = (size_t)(m0 + row) * K + k0 + c8;
        size_t gb = (size_t)(n0 + row) * K + k0 + c8;
        CP16(base + OFF_AH + off, &AHg[ga]);
        CP16(base + OFF_AL + off, &ALg[ga]);
        CP16(base + OFF_BH + off, &BHg[gb]);
        CP16(base + OFF_BL + off, &BLg[gb]);
    }
}

template<bool OSPLIT>
__global__ __launch_bounds__(256) void gemm_mma(
    const __nv_bfloat16* __restrict__ AHg, const __nv_bfloat16* __restrict__ ALg,
    const __nv_bfloat16* __restrict__ BHg, const __nv_bfloat16* __restrict__ BLg,
    const float* __restrict__ bias, float scale,
    float* __restrict__ Cf,
    __nv_bfloat16* __restrict__ CHg, __nv_bfloat16* __restrict__ CLg,
    int M, int N, int K)
{
    extern __shared__ char sm[];
    const uint32_t sb = smem_u32(sm);
    const int tid  = threadIdx.x;
    const int lane = tid & 31;
    const int wid  = tid >> 5;
    const int wm   = (wid & 3) * 32;
    const int wn   = (wid >> 2) * 64;
    const int m0   = blockIdx.y * 128;
    const int n0   = blockIdx.x * 128;
    const int sel  = lane >> 3;
    const int l7   = lane & 7;

    float cacc[2][8][4];
    #pragma unroll
    for (int mt = 0; mt < 2; mt++)
        #pragma unroll
        for (int nt = 0; nt < 8; nt++)
            #pragma unroll
            for (int i = 0; i < 4; i++) cacc[mt][nt][i] = 0.f;

    const int nch = K >> 6;
    gemm_prefetch(sb, 0, tid, m0, n0, 0, K, AHg, ALg, BHg, BLg);
    CP_COMMIT();

    for (int ch = 0; ch < nch; ch++) {
        if (ch + 1 < nch) {
            gemm_prefetch(sb, (ch + 1) & 1, tid, m0, n0, (ch + 1) << 6, K,
                          AHg, ALg, BHg, BLg);
            CP_COMMIT();
            CP_WAIT(1);
        } else {
            CP_WAIT(0);
        }
        __syncthreads();

        const uint32_t st = sb + (ch & 1) * STG;
        #pragma unroll
        for (int ks = 0; ks < 4; ks++) {
            const uint32_t unit = ks * 2 + (sel >> 1);
            uint32_t ah[2][4], al[2][4];
            #pragma unroll
            for (int mt = 0; mt < 2; mt++) {
                uint32_t rowA = wm + mt * 16 + ((sel & 1) << 3) + l7;
                uint32_t off  = rowA * 128 + ((unit ^ (rowA & 7)) << 4);
                LDSM_X4(ah[mt][0], ah[mt][1], ah[mt][2], ah[mt][3], st + OFF_AH + off);
                LDSM_X4(al[mt][0], al[mt][1], al[mt][2], al[mt][3], st + OFF_AL + off);
            }
            #pragma unroll
            for (int ntp = 0; ntp < 4; ntp++) {
                uint32_t rowB = wn + ntp * 16 + ((sel & 1) << 3) + l7;
                uint32_t off  = rowB * 128 + ((unit ^ (rowB & 7)) << 4);
                uint32_t bh0, bh1, bh2, bh3, bl0, bl1, bl2, bl3;
                LDSM_X4(bh0, bh1, bh2, bh3, st + OFF_BH + off);
                LDSM_X4(bl0, bl1, bl2, bl3, st + OFF_BL + off);
                #pragma unroll
                for (int mt = 0; mt < 2; mt++) {
                    MMA_BF16(cacc[mt][2 * ntp],     ah[mt], bh0, bh2);
                    MMA_BF16(cacc[mt][2 * ntp],     ah[mt], bl0, bl2);
                    MMA_BF16(cacc[mt][2 * ntp],     al[mt], bh0, bh2);
                    MMA_BF16(cacc[mt][2 * ntp + 1], ah[mt], bh1, bh3);
                    MMA_BF16(cacc[mt][2 * ntp + 1], ah[mt], bl1, bl3);
                    MMA_BF16(cacc[mt][2 * ntp + 1], al[mt], bh1, bh3);
                }
            }
        }
        __syncthreads();
    }

    // ---- epilogue ----
    #pragma unroll
    for (int mt = 0; mt < 2; mt++) {
        int row = m0 + wm + mt * 16 + (lane >> 2);
        #pragma unroll
        for (int nt = 0; nt < 8; nt++) {
            int col = n0 + wn + nt * 8 + ((lane & 3) << 1);
            float bx = bias[col], by = bias[col + 1];
            float v0 = (cacc[mt][nt][0] + bx) * scale;
            float v1 = (cacc[mt][nt][1] + by) * scale;
            float v2 = (cacc[mt][nt][2] + bx) * scale;
            float v3 = (cacc[mt][nt][3] + by) * scale;
            if (OSPLIT) {
                __nv_bfloat162 h01 = __floats2bfloat162_rn(v0, v1);
                __nv_bfloat162 h23 = __floats2bfloat162_rn(v2, v3);
                __nv_bfloat162 l01 = __floats2bfloat162_rn(
                    v0 - __bfloat162float(h01.x), v1 - __bfloat162float(h01.y));
                __nv_bfloat162 l23 = __floats2bfloat162_rn(
                    v2 - __bfloat162float(h23.x), v3 - __bfloat162float(h23.y));
                *(__nv_bfloat162*)&CHg[(size_t)row * N + col]       = h01;
                *(__nv_bfloat162*)&CHg[(size_t)(row + 8) * N + col] = h23;
                *(__nv_bfloat162*)&CLg[(size_t)row * N + col]       = l01;
                *(__nv_bfloat162*)&CLg[(size_t)(row + 8) * N + col] = l23;
            } else {
                float2 a = {v0, v1}, b = {v2, v3};
                *(float2*)&Cf[(size_t)row * N + col]       = a;
                *(float2*)&Cf[(size_t)(row + 8) * N + col] = b;
            }
        }
    }
}

// ---------------------------------------------------------------------------
// Flash attention, split-bf16 mma.sync, poly-exp softmax, cp.async 2-stage.
// 128 threads (4 warps), 64-query tile. Output split bf16 hi/lo.
// Dynamic smem: 2 stages x (KH,KL,VH,VL 8KB each) = 64KB.
// ---------------------------------------------------------------------------
#define ASTG 32768
#define AOFF_KH 0
#define AOFF_KL 8192
#define AOFF_VH 16384
#define AOFF_VL 24576
#define ATTN_SMEM (2 * ASTG)

__device__ __forceinline__ void attn_prefetch(
    uint32_t sb, int stage, int tid, size_t rowbase,
    const __nv_bfloat16* KHg, const __nv_bfloat16* KLg,
    const __nv_bfloat16* VHg, const __nv_bfloat16* VLg)
{
    const uint32_t base = sb + stage * ASTG;
    #pragma unroll
    for (int it = 0; it < 4; it++) {
        int idx = it * 128 + tid;           // 512 chunks per array
        int j = idx >> 3, c8 = (idx & 7) << 3;
        size_t g = rowbase + (size_t)j * D_MODEL + c8;
        uint32_t off = j * 128 + ((((c8 >> 3) ^ (j & 7))) << 4);
        CP16(base + AOFF_KH + off, &KHg[g]);
        CP16(base + AOFF_KL + off, &KLg[g]);
        CP16(base + AOFF_VH + off, &VHg[g]);
        CP16(base + AOFF_VL + off, &VLg[g]);
    }
}

__global__ __launch_bounds__(128) void attn_mma_kernel(
    const __nv_bfloat16* __restrict__ QHg, const __nv_bfloat16* __restrict__ QLg,
    const __nv_bfloat16* __restrict__ KHg, const __nv_bfloat16* __restrict__ KLg,
    const __nv_bfloat16* __restrict__ VHg, const __nv_bfloat16* __restrict__ VLg,
    __nv_bfloat16* __restrict__ OH, __nv_bfloat16* __restrict__ OL)
{
    extern __shared__ char asm_[];
    const uint32_t sb = smem_u32(asm_);

    const int tid  = threadIdx.x;
    const int lane = tid & 31;
    const int warp = tid >> 5;
    const int tile = gridDim.x - 1 - blockIdx.x;
    const int h    = blockIdx.y;
    const int b    = blockIdx.z;
    const int base = b * SEQ;
    const int sel  = lane >> 3;
    const int l7   = lane & 7;
    const int wq   = warp * 16;

    // ---- stage Q into stage-1 KH/KL area, extract A-frags ----
    {
        const uint32_t qb = sb + ASTG;
        #pragma unroll
        for (int it = 0; it < 4; it++) {
            int idx = it * 128 + tid;
            int r = idx >> 3, c8 = (idx & 7) << 3;
            size_t g = (size_t)(base + tile * 64 + r) * D_MODEL + h * D_K + c8;
            uint32_t off = r * 128 + ((((c8 >> 3) ^ (r & 7))) << 4);
            CP16(qb + AOFF_KH + off, &QHg[g]);
            CP16(qb + AOFF_KL + off, &QLg[g]);
        }
        CP_COMMIT();
        CP_WAIT(0);
        __syncthreads();
    }
    uint32_t qh[4][4], ql[4][4];
    #pragma unroll
    for (int kc = 0; kc < 4; kc++) {
        uint32_t row = wq + ((sel & 1) << 3) + l7;
        uint32_t off = row * 128 + ((((uint32_t)(kc * 2 + (sel >> 1)) ^ (row & 7))) << 4);
        LDSM_X4(qh[kc][0], qh[kc][1], qh[kc][2], qh[kc][3], sb + ASTG + AOFF_KH + off);
        LDSM_X4(ql[kc][0], ql[kc][1], ql[kc][2], ql[kc][3], sb + ASTG + AOFF_KL + off);
    }
    __syncthreads();

    float oacc[8][4];
    #pragma unroll
    for (int ng = 0; ng < 8; ng++)
        #pragma unroll
        for (int i = 0; i < 4; i++) oacc[ng][i] = 0.f;
    float mrow[2] = {-1e30f, -1e30f};
    float lrow[2] = {0.f, 0.f};

    attn_prefetch(sb, 0, tid, (size_t)base * D_MODEL + h * D_K, KHg, KLg, VHg, VLg);
    CP_COMMIT();

    for (int t = 0; t <= tile; t++) {
        if (t < tile) {
            attn_prefetch(sb, (t + 1) & 1, tid,
                          (size_t)(base + (t + 1) * 64) * D_MODEL + h * D_K,
                          KHg, KLg, VHg, VLg);
            CP_COMMIT();
            CP_WAIT(1);
        } else {
            CP_WAIT(0);
        }
        __syncthreads();
        const uint32_t st = sb + (t & 1) * ASTG;

        // ---- S = Q @ K^T ----
        float sacc[8][4];
        #pragma unroll
        for (int nt = 0; nt < 8; nt++)
            #pragma unroll
            for (int i = 0; i < 4; i++) sacc[nt][i] = 0.f;

        #pragma unroll
        for (int kc = 0; kc < 4; kc++) {
            const uint32_t unit = kc * 2 + (sel >> 1);
            #pragma unroll
            for (int ntp = 0; ntp < 4; ntp++) {
                uint32_t rowB = ntp * 16 + ((sel & 1) << 3) + l7;
                uint32_t off  = rowB * 128 + ((unit ^ (rowB & 7)) << 4);
                uint32_t bh0, bh1, bh2, bh3, bl0, bl1, bl2, bl3;
                LDSM_X4(bh0, bh1, bh2, bh3, st + AOFF_KH + off);
                LDSM_X4(bl0, bl1, bl2, bl3, st + AOFF_KL + off);
                MMA_BF16(sacc[2 * ntp],     qh[kc], bh0, bh2);
                MMA_BF16(sacc[2 * ntp],     qh[kc], bl0, bl2);
                MMA_BF16(sacc[2 * ntp],     ql[kc], bh0, bh2);
                MMA_BF16(sacc[2 * ntp + 1], qh[kc], bh1, bh3);
                MMA_BF16(sacc[2 * ntp + 1], qh[kc], bl1, bl3);
                MMA_BF16(sacc[2 * ntp + 1], ql[kc], bh1, bh3);
            }
        }

        // ---- causal mask on diagonal tile ----
        if (t == tile) {
            int r0 = wq + (lane >> 2);
            #pragma unroll
            for (int nt = 0; nt < 8; nt++) {
                int cb = nt * 8 + ((lane & 3) << 1);
                if (cb     > r0)     sacc[nt][0] = -1e30f;
                if (cb + 1 > r0)     sacc[nt][1] = -1e30f;
                if (cb     > r0 + 8) sacc[nt][2] = -1e30f;
                if (cb + 1 > r0 + 8) sacc[nt][3] = -1e30f;
            }
        }

        // ---- online softmax ----
        #pragma unroll
        for (int ri = 0; ri < 2; ri++) {
            const int e0 = ri * 2, e1 = ri * 2 + 1;
            float rm = -1e30f;
            #pragma unroll
            for (int nt = 0; nt < 8; nt++)
                rm = fmaxf(rm, fmaxf(sacc[nt][e0], sacc[nt][e1]));
            rm = fmaxf(rm, __shfl_xor_sync(0xffffffffu, rm, 1));
            rm = fmaxf(rm, __shfl_xor_sync(0xffffffffu, rm, 2));
            float mn = fmaxf(mrow[ri], rm);
            float corr = fexp(mrow[ri] - mn);
            mrow[ri] = mn;
            lrow[ri] *= corr;
            #pragma unroll
            for (int ng = 0; ng < 8; ng++) {
                oacc[ng][e0] *= corr;
                oacc[ng][e1] *= corr;
            }
            float ls = 0.f;
            #pragma unroll
            for (int nt = 0; nt < 8; nt++) {
                float p0 = fexp(sacc[nt][e0] - mn);
                float p1 = fexp(sacc[nt][e1] - mn);
                sacc[nt][e0] = p0;
                sacc[nt][e1] = p1;
                ls += p0 + p1;
            }
            lrow[ri] += ls;
        }

        // ---- O += P @ V ----
        #pragma unroll
        for (int kc = 0; kc < 4; kc++) {
            uint32_t aH[4], aL[4];
            {
                float c0 = sacc[2 * kc][0],     c1 = sacc[2 * kc][1];
                float c2 = sacc[2 * kc][2],     c3 = sacc[2 * kc][3];
                float d0 = sacc[2 * kc + 1][0], d1 = sacc[2 * kc + 1][1];
                float d2 = sacc[2 * kc + 1][2], d3 = sacc[2 * kc + 1][3];
                aH[0] = pack_bf2(c0, c1);
                aH[1] = pack_bf2(c2, c3);
                aH[2] = pack_bf2(d0, d1);
                aH[3] = pack_bf2(d2, d3);
                __nv_bfloat162 h0 = *(__nv_bfloat162*)&aH[0];
                __nv_bfloat162 h1 = *(__nv_bfloat162*)&aH[1];
                __nv_bfloat162 h2 = *(__nv_bfloat162*)&aH[2];
                __nv_bfloat162 h3 = *(__nv_bfloat162*)&aH[3];
                aL[0] = pack_bf2(c0 - __bfloat162float(h0.x), c1 - __bfloat162float(h0.y));
                aL[1] = pack_bf2(c2 - __bfloat162float(h1.x), c3 - __bfloat162float(h1.y));
                aL[2] = pack_bf2(d0 - __bfloat162float(h2.x), d1 - __bfloat162float(h2.y));
                aL[3] = pack_bf2(d2 - __bfloat162float(h3.x), d3 - __bfloat162float(h3.y));
            }
            #pragma unroll
            for (int dp = 0; dp < 4; dp++) {
                uint32_t rowV = kc * 16 + ((sel & 1) << 3) + l7;
                uint32_t unit = dp * 2 + (sel >> 1);
                uint32_t off  = rowV * 128 + ((unit ^ (rowV & 7)) << 4);
                uint32_t vh0, vh1, vh2, vh3, vl0, vl1, vl2, vl3;
                LDSM_X4_T(vh0, vh1, vh2, vh3, st + AOFF_VH + off);
                LDSM_X4_T(vl0, vl1, vl2, vl3, st + AOFF_VL + off);
                MMA_BF16(oacc[2 * dp],     aH, vh0, vh1);
                MMA_BF16(oacc[2 * dp],     aH, vl0, vl1);
                MMA_BF16(oacc[2 * dp],     aL, vh0, vh1);
                MMA_BF16(oacc[2 * dp + 1], aH, vh2, vh3);
                MMA_BF16(oacc[2 * dp + 1], aH, vl2, vl3);
                MMA_BF16(oacc[2 * dp + 1], aL, vh2, vh3);
            }
        }
        __syncthreads();
    }

    // ---- finalize: split bf16 output ----
    #pragma unroll
    for (int ri = 0; ri < 2; ri++) {
        lrow[ri] += __shfl_xor_sync(0xffffffffu, lrow[ri], 1);
        lrow[ri] += __shfl_xor_sync(0xffffffffu, lrow[ri], 2);
    }
    float inv0 = 1.f / lrow[0], inv1 = 1.f / lrow[1];
    int row0 = base + tile * 64 + wq + (lane >> 2);
    #pragma unroll
    for (int ng = 0; ng < 8; ng++) {
        int col = h * D_K + ng * 8 + ((lane & 3) << 1);
        float v0 = oacc[ng][0] * inv0, v1 = oacc[ng][1] * inv0;
        float v2 = oacc[ng][2] * inv1, v3 = oacc[ng][3] * inv1;
        __nv_bfloat162 h01 = __floats2bfloat162_rn(v0, v1);
        __nv_bfloat162 h23 = __floats2bfloat162_rn(v2, v3);
        __nv_bfloat162 l01 = __floats2bfloat162_rn(
            v0 - __bfloat162float(h01.x), v1 - __bfloat162float(h01.y));
        __nv_bfloat162 l23 = __floats2bfloat162_rn(
            v2 - __bfloat162float(h23.x), v3 - __bfloat162float(h23.y));
        *(__nv_bfloat162*)&OH[(size_t)row0 * D_MODEL + col]       = h01;
        *(__nv_bfloat162*)&OH[(size_t)(row0 + 8) * D_MODEL + col] = h23;
        *(__nv_bfloat162*)&OL[(size_t)row0 * D_MODEL + col]       = l01;
        *(__nv_bfloat162*)&OL[(size_t)(row0 + 8) * D_MODEL + col] = l23;
    }
}

// ---------------------------------------------------------------------------
// Launch
// ---------------------------------------------------------------------------
extern "C" void kernel_launch(void* const* d_in, const int* in_sizes, int n_in,
                              void* d_out, int out_size)
{
    const float* queries = (const float*)d_in[0];
    const float* keys    = (const float*)d_in[1];
    // d_in[2] = values (unused by reference)
    const float* Wq = (const float*)d_in[3];
    const float* bq = (const float*)d_in[4];
    const float* Wd = (const float*)d_in[5];
    const float* bd = (const float*)d_in[6];
    const float* Wk = (const float*)d_in[7];
    const float* bk = (const float*)d_in[8];
    const float* Wv = (const float*)d_in[9];
    const float* bv = (const float*)d_in[10];
    const float* Wo = (const float*)d_in[11];
    const float* bo = (const float*)d_in[12];
    float* out = (float*)d_out;

    __nv_bfloat16 *pQinH, *pQinL, *pKinH, *pKinL;
    __nv_bfloat16 *pLatH, *pLatL, *pQH, *pQL, *pKH, *pKL, *pVH, *pVL, *pOH, *pOL;
    __nv_bfloat16 *pWqTH, *pWqTL, *pWdTH, *pWdTL, *pWkTH, *pWkTL, *pWvTH, *pWvTL, *pWoTH, *pWoTL;
    cudaGetSymbolAddress((void**)&pQinH, g_qinH);
    cudaGetSymbolAddress((void**)&pQinL, g_qinL);
    cudaGetSymbolAddress((void**)&pKinH, g_kinH);
    cudaGetSymbolAddress((void**)&pKinL, g_kinL);
    cudaGetSymbolAddress((void**)&pLatH, g_latH);
    cudaGetSymbolAddress((void**)&pLatL, g_latL);
    cudaGetSymbolAddress((void**)&pQH, g_QH);
    cudaGetSymbolAddress((void**)&pQL, g_QL);
    cudaGetSymbolAddress((void**)&pKH, g_KH);
    cudaGetSymbolAddress((void**)&pKL, g_KL);
    cudaGetSymbolAddress((void**)&pVH, g_VH);
    cudaGetSymbolAddress((void**)&pVL, g_VL);
    cudaGetSymbolAddress((void**)&pOH, g_OH);
    cudaGetSymbolAddress((void**)&pOL, g_OL);
    cudaGetSymbolAddress((void**)&pWqTH, g_WqTH);
    cudaGetSymbolAddress((void**)&pWqTL, g_WqTL);
    cudaGetSymbolAddress((void**)&pWdTH, g_WdTH);
    cudaGetSymbolAddress((void**)&pWdTL, g_WdTL);
    cudaGetSymbolAddress((void**)&pWkTH, g_WkTH);
    cudaGetSymbolAddress((void**)&pWkTL, g_WkTL);
    cudaGetSymbolAddress((void**)&pWvTH, g_WvTH);
    cudaGetSymbolAddress((void**)&pWvTL, g_WvTL);
    cudaGetSymbolAddress((void**)&pWoTH, g_WoTH);
    cudaGetSymbolAddress((void**)&pWoTL, g_WoTL);

    cudaFuncSetAttribute(gemm_mma<true>,
                         cudaFuncAttributeMaxDynamicSharedMemorySize, GEMM_SMEM);
    cudaFuncSetAttribute(gemm_mma<false>,
                         cudaFuncAttributeMaxDynamicSharedMemorySize, GEMM_SMEM);
    cudaFuncSetAttribute(attn_mma_kernel,
                         cudaFuncAttributeMaxDynamicSharedMemorySize, ATTN_SMEM);

    // input splits
    split_kernel<<<1024, 256>>>(queries, pQinH, pQinL, ROWS * D_MODEL / 4);
    split_kernel<<<1024, 256>>>(keys,    pKinH, pKinL, ROWS * D_MODEL / 4);

    dim3 tb(32, 8);
    transpose_split_kernel<<<dim3(D_MODEL/32, D_MODEL/32), tb>>>(Wq, pWqTH, pWqTL, D_MODEL, D_MODEL);
    transpose_split_kernel<<<dim3(LATENT/32,  D_MODEL/32), tb>>>(Wd, pWdTH, pWdTL, D_MODEL, LATENT);
    transpose_split_kernel<<<dim3(D_MODEL/32, LATENT/32),  tb>>>(Wk, pWkTH, pWkTL, LATENT, D_MODEL);
    transpose_split_kernel<<<dim3(D_MODEL/32, LATENT/32),  tb>>>(Wv, pWvTH, pWvTL, LATENT, D_MODEL);
    transpose_split_kernel<<<dim3(D_MODEL/32, D_MODEL/32), tb>>>(Wo, pWoTH, pWoTL, D_MODEL, D_MODEL);

    // 1) latent = keys @ Wd + bd
    gemm_mma<true><<<dim3(LATENT/128, ROWS/128), 256, GEMM_SMEM>>>(
        pKinH, pKinL, pWdTH, pWdTL, bd, 1.f,
        nullptr, pLatH, pLatL, ROWS, LATENT, D_MODEL);
    // 2) Q = (queries @ Wq + bq) * 0.125
    gemm_mma<true><<<dim3(D_MODEL/128, ROWS/128), 256, GEMM_SMEM>>>(
        pQinH, pQinL, pWqTH, pWqTL, bq, 0.125f,
        nullptr, pQH, pQL, ROWS, D_MODEL, D_MODEL);
    // 3) K = latent @ Wk + bk
    gemm_mma<true><<<dim3(D_MODEL/128, ROWS/128), 256, GEMM_SMEM>>>(
        pLatH, pLatL, pWkTH, pWkTL, bk, 1.f,
        nullptr, pKH, pKL, ROWS, D_MODEL, LATENT);
    // 4) V = latent @ Wv + bv
    gemm_mma<true><<<dim3(D_MODEL/128, ROWS/128), 256, GEMM_SMEM>>>(
        pLatH, pLatL, pWvTH, pWvTL, bv, 1.f,
        nullptr, pVH, pVL, ROWS, D_MODEL, LATENT);
    // 5) attention (split output)
    attn_mma_kernel<<<dim3(SEQ/64, N_HEADS, BATCH), 128, ATTN_SMEM>>>(
        pQH, pQL, pKH, pKL, pVH, pVL, pOH, pOL);
    // 6) out = O @ Wo + bo
    gemm_mma<false><<<dim3(D_MODEL/128, ROWS/128), 256, GEMM_SMEM>>>(
        pOH, pOL, pWoTH, pWoTL, bo, 1.f,
        out, nullptr, nullptr, ROWS, D_MODEL, D_MODEL);
}

// round 9
// speedup vs baseline: 3.5898x; 1.0386x over previous
#include <cuda_runtime.h>
#include <cuda_bf16.h>
#include <math.h>
#include <stdint.h>

// Problem constants
#define D_MODEL 1024
#define N_HEADS 16
#define D_K     64
#define LATENT  256
#define BATCH   2
#define SEQ     2048
#define ROWS    (BATCH * SEQ)   // 4096

// ---------------------------------------------------------------------------
// Scratch (device globals)
// ---------------------------------------------------------------------------
__device__ __nv_bfloat16 g_qinH[ROWS * D_MODEL], g_qinL[ROWS * D_MODEL];
__device__ __nv_bfloat16 g_kinH[ROWS * D_MODEL], g_kinL[ROWS * D_MODEL];
__device__ __nv_bfloat16 g_latH[ROWS * LATENT], g_latL[ROWS * LATENT];
__device__ __nv_bfloat16 g_QH[ROWS * D_MODEL], g_QL[ROWS * D_MODEL];
__device__ __nv_bfloat16 g_KH[ROWS * D_MODEL], g_KL[ROWS * D_MODEL];
__device__ __nv_bfloat16 g_VH[ROWS * D_MODEL], g_VL[ROWS * D_MODEL];
__device__ __nv_bfloat16 g_OH[ROWS * D_MODEL], g_OL[ROWS * D_MODEL];
// pre-split transposed weights [N][K] bf16 hi/lo
__device__ __nv_bfloat16 g_WqTH[D_MODEL * D_MODEL], g_WqTL[D_MODEL * D_MODEL];
__device__ __nv_bfloat16 g_WdTH[LATENT * D_MODEL],  g_WdTL[LATENT * D_MODEL];
__device__ __nv_bfloat16 g_WkTH[D_MODEL * LATENT],  g_WkTL[D_MODEL * LATENT];
__device__ __nv_bfloat16 g_WvTH[D_MODEL * LATENT],  g_WvTL[D_MODEL * LATENT];
__device__ __nv_bfloat16 g_WoTH[D_MODEL * D_MODEL], g_WoTL[D_MODEL * D_MODEL];

__device__ __forceinline__ uint32_t smem_u32(const void* p) {
    uint32_t a;
    asm("{ .reg .u64 t; cvta.to.shared.u64 t, %1; cvt.u32.u64 %0, t; }"
        : "=r"(a) : "l"(p));
    return a;
}

#define LDSM_X4(r0, r1, r2, r3, addr) \
    asm volatile("ldmatrix.sync.aligned.m8n8.x4.shared.b16 {%0,%1,%2,%3}, [%4];" \
        : "=r"(r0), "=r"(r1), "=r"(r2), "=r"(r3) : "r"(addr))

#define LDSM_X4_T(r0, r1, r2, r3, addr) \
    asm volatile("ldmatrix.sync.aligned.m8n8.x4.trans.shared.b16 {%0,%1,%2,%3}, [%4];" \
        : "=r"(r0), "=r"(r1), "=r"(r2), "=r"(r3) : "r"(addr))

#define MMA_BF16(c, a, b0v, b1v) \
    asm volatile("mma.sync.aligned.m16n8k16.row.col.f32.bf16.bf16.f32 " \
        "{%0,%1,%2,%3}, {%4,%5,%6,%7}, {%8,%9}, {%0,%1,%2,%3};" \
        : "+f"((c)[0]), "+f"((c)[1]), "+f"((c)[2]), "+f"((c)[3]) \
        : "r"((a)[0]), "r"((a)[1]), "r"((a)[2]), "r"((a)[3]), "r"(b0v), "r"(b1v))

#define CP16(dst, src) \
    asm volatile("cp.async.cg.shared.global [%0], [%1], 16;" \
        :: "r"(dst), "l"(src) : "memory")
#define CP_COMMIT() asm volatile("cp.async.commit_group;" ::: "memory")
#define CP_WAIT(n)  asm volatile("cp.async.wait_group %0;" :: "n"(n) : "memory")

// Fast exp on FMA/ALU pipes (no MUFU). Valid for x <= 0 (clamped at -80).
__device__ __forceinline__ float fexp(float x) {
    x = fmaxf(x, -80.f);
    float t2 = x * 1.4426950408889634f;
    float r  = t2 + 12582912.f;
    int   n  = __float_as_int(r) - 0x4B400000;
    float f  = t2 - (r - 12582912.f);
    float p  = fmaf(f, 0.0096181291f, 0.0555041087f);
    p = fmaf(f, p, 0.2402265069f);
    p = fmaf(f, p, 0.6931471806f);
    p = fmaf(f, p, 1.0f);
    return p * __int_as_float((127 + n) << 23);
}

__device__ __forceinline__ uint32_t pack_bf2(float a, float b) {
    __nv_bfloat162 t = __floats2bfloat162_rn(a, b);
    return *(uint32_t*)&t;
}

// ---------------------------------------------------------------------------
// Fused preprocessing: input splits + weight transpose-splits, one launch.
// Block ranges:
//   [0,1024)      split queries  (1024 f4 per block)
//   [1024,2048)   split keys
//   [2048,3072)   transpose Wq   (32x32 blocks)
//   [3072,3328)   transpose Wd   (8x32)
//   [3328,3584)   transpose Wk   (32x8)
//   [3584,3840)   transpose Wv   (32x8)
//   [3840,4864)   transpose Wo   (32x32)
// ---------------------------------------------------------------------------
__device__ __forceinline__ void do_split_range(
    const float* __restrict__ X, __nv_bfloat16* __restrict__ H,
    __nv_bfloat16* __restrict__ L, int blk)
{
    int base = blk * 1024 + threadIdx.x;
    #pragma unroll
    for (int i = 0; i < 4; i++) {
        int idx = base + i * 256;
        float4 v = ((const float4*)X)[idx];
        float a[4] = {v.x, v.y, v.z, v.w};
        union { __nv_bfloat16 b[4]; uint2 u; } hh, ll;
        #pragma unroll
        for (int c = 0; c < 4; c++) {
            hh.b[c] = __float2bfloat16(a[c]);
            ll.b[c] = __float2bfloat16(a[c] - __bfloat162float(hh.b[c]));
        }
        ((uint2*)H)[idx] = hh.u;
        ((uint2*)L)[idx] = ll.u;
    }
}

__device__ __forceinline__ void do_transpose_split(
    const float* __restrict__ W, __nv_bfloat16* __restrict__ WtH,
    __nv_bfloat16* __restrict__ WtL, int K, int N, int bx, int by)
{
    __shared__ float t[32][33];
    int kb = by * 32, nb = bx * 32;
    int x = threadIdx.x & 31, y = threadIdx.x >> 5;   // 32 x 8
    #pragma unroll
    for (int i = 0; i < 32; i += 8)
        t[y + i][x] = W[(size_t)(kb + y + i) * N + nb + x];
    __syncthreads();
    #pragma unroll
    for (int i = 0; i < 32; i += 8) {
        float v = t[x][y + i];
        __nv_bfloat16 h = __float2bfloat16(v);
        WtH[(size_t)(nb + y + i) * K + kb + x] = h;
        WtL[(size_t)(nb + y + i) * K + kb + x] =
            __float2bfloat16(v - __bfloat162float(h));
    }
}

__global__ __launch_bounds__(256) void preproc_kernel(
    const float* __restrict__ queries, const float* __restrict__ keys,
    const float* __restrict__ Wq, const float* __restrict__ Wd,
    const float* __restrict__ Wk, const float* __restrict__ Wv,
    const float* __restrict__ Wo,
    __nv_bfloat16* qinH, __nv_bfloat16* qinL,
    __nv_bfloat16* kinH, __nv_bfloat16* kinL,
    __nv_bfloat16* WqTH, __nv_bfloat16* WqTL,
    __nv_bfloat16* WdTH, __nv_bfloat16* WdTL,
    __nv_bfloat16* WkTH, __nv_bfloat16* WkTL,
    __nv_bfloat16* WvTH, __nv_bfloat16* WvTL,
    __nv_bfloat16* WoTH, __nv_bfloat16* WoTL)
{
    int b = blockIdx.x;
    if (b < 1024) {
        do_split_range(queries, qinH, qinL, b);
    } else if (b < 2048) {
        do_split_range(keys, kinH, kinL, b - 1024);
    } else if (b < 3072) {
        int t = b - 2048;
        do_transpose_split(Wq, WqTH, WqTL, D_MODEL, D_MODEL, t & 31, t >> 5);
    } else if (b < 3328) {
        int t = b - 3072;
        do_transpose_split(Wd, WdTH, WdTL, D_MODEL, LATENT, t & 7, t >> 3);
    } else if (b < 3584) {
        int t = b - 3328;
        do_transpose_split(Wk, WkTH, WkTL, LATENT, D_MODEL, t & 31, t >> 5);
    } else if (b < 3840) {
        int t = b - 3584;
        do_transpose_split(Wv, WvTH, WvTL, LATENT, D_MODEL, t & 31, t >> 5);
    } else {
        int t = b - 3840;
        do_transpose_split(Wo, WoTH, WoTL, D_MODEL, D_MODEL, t & 31, t >> 5);
    }
}

// ---------------------------------------------------------------------------
// Dual-job split-bf16 tensor-core GEMM, cp.async double-buffered.
// blockIdx.x < nx0 -> job0, else job1. Both jobs share M.
// 128x128 CTA, BK=64, 256 threads (8 warps, 32x64 warp tile), 2 stages.
// ---------------------------------------------------------------------------
#define STG 65536
#define OFF_AH 0
#define OFF_AL 16384
#define OFF_BH 32768
#define OFF_BL 49152
#define GEMM_SMEM (2 * STG)

__device__ __forceinline__ void gemm_prefetch(
    uint32_t sb, int stage, int tid, int m0, int n0, int k0, int K,
    const __nv_bfloat16* AHg, const __nv_bfloat16* ALg,
    const __nv_bfloat16* BHg, const __nv_bfloat16* BLg)
{
    const uint32_t base = sb + stage * STG;
    #pragma unroll
    for (int it = 0; it < 4; it++) {
        int idx = it * 256 + tid;
        int row = idx >> 3, c8 = (idx & 7) << 3;
        uint32_t off = row * 128 + ((((c8 >> 3) ^ (row & 7))) << 4);
        size_t ga = (size_t)(m0 + row) * K + k0 + c8;
        size_t gb = (size_t)(n0 + row) * K + k0 + c8;
        CP16(base + OFF_AH + off, &AHg[ga]);
        CP16(base + OFF_AL + off, &ALg[ga]);
        CP16(base + OFF_BH + off, &BHg[gb]);
        CP16(base + OFF_BL + off, &BLg[gb]);
    }
}

template<bool OSPLIT>
__global__ __launch_bounds__(256) void gemm_dual(
    int nx0,
    const __nv_bfloat16* __restrict__ AH0, const __nv_bfloat16* __restrict__ AL0,
    const __nv_bfloat16* __restrict__ BH0, const __nv_bfloat16* __restrict__ BL0,
    const float* __restrict__ bias0, float scale0,
    float* __restrict__ Cf0, __nv_bfloat16* __restrict__ CH0, __nv_bfloat16* __restrict__ CL0,
    int N0, int K0,
    const __nv_bfloat16* __restrict__ AH1, const __nv_bfloat16* __restrict__ AL1,
    const __nv_bfloat16* __restrict__ BH1, const __nv_bfloat16* __restrict__ BL1,
    const float* __restrict__ bias1, float scale1,
    float* __restrict__ Cf1, __nv_bfloat16* __restrict__ CH1, __nv_bfloat16* __restrict__ CL1,
    int N1, int K1)
{
    extern __shared__ char sm[];
    const uint32_t sb = smem_u32(sm);
    const int tid  = threadIdx.x;
    const int lane = tid & 31;
    const int wid  = tid >> 5;
    const int wm   = (wid & 3) * 32;
    const int wn   = (wid >> 2) * 64;
    const int m0   = blockIdx.y * 128;
    const int sel  = lane >> 3;
    const int l7   = lane & 7;

    const bool j1 = (blockIdx.x >= (unsigned)nx0);
    const __nv_bfloat16* AHg = j1 ? AH1 : AH0;
    const __nv_bfloat16* ALg = j1 ? AL1 : AL0;
    const __nv_bfloat16* BHg = j1 ? BH1 : BH0;
    const __nv_bfloat16* BLg = j1 ? BL1 : BL0;
    const float* bias = j1 ? bias1 : bias0;
    const float scale = j1 ? scale1 : scale0;
    float* Cf = j1 ? Cf1 : Cf0;
    __nv_bfloat16* CHg = j1 ? CH1 : CH0;
    __nv_bfloat16* CLg = j1 ? CL1 : CL0;
    const int N = j1 ? N1 : N0;
    const int K = j1 ? K1 : K0;
    const int n0 = (j1 ? (blockIdx.x - nx0) : blockIdx.x) * 128;

    float cacc[2][8][4];
    #pragma unroll
    for (int mt = 0; mt < 2; mt++)
        #pragma unroll
        for (int nt = 0; nt < 8; nt++)
            #pragma unroll
            for (int i = 0; i < 4; i++) cacc[mt][nt][i] = 0.f;

    const int nch = K >> 6;
    gemm_prefetch(sb, 0, tid, m0, n0, 0, K, AHg, ALg, BHg, BLg);
    CP_COMMIT();

    for (int ch = 0; ch < nch; ch++) {
        if (ch + 1 < nch) {
            gemm_prefetch(sb, (ch + 1) & 1, tid, m0, n0, (ch + 1) << 6, K,
                          AHg, ALg, BHg, BLg);
            CP_COMMIT();
            CP_WAIT(1);
        } else {
            CP_WAIT(0);
        }
        __syncthreads();

        const uint32_t st = sb + (ch & 1) * STG;
        #pragma unroll
        for (int ks = 0; ks < 4; ks++) {
            const uint32_t unit = ks * 2 + (sel >> 1);
            uint32_t ah[2][4], al[2][4];
            #pragma unroll
            for (int mt = 0; mt < 2; mt++) {
                uint32_t rowA = wm + mt * 16 + ((sel & 1) << 3) + l7;
                uint32_t off  = rowA * 128 + ((unit ^ (rowA & 7)) << 4);
                LDSM_X4(ah[mt][0], ah[mt][1], ah[mt][2], ah[mt][3], st + OFF_AH + off);
                LDSM_X4(al[mt][0], al[mt][1], al[mt][2], al[mt][3], st + OFF_AL + off);
            }
            #pragma unroll
            for (int ntp = 0; ntp < 4; ntp++) {
                uint32_t rowB = wn + ntp * 16 + ((sel & 1) << 3) + l7;
                uint32_t off  = rowB * 128 + ((unit ^ (rowB & 7)) << 4);
                uint32_t bh0, bh1, bh2, bh3, bl0, bl1, bl2, bl3;
                LDSM_X4(bh0, bh1, bh2, bh3, st + OFF_BH + off);
                LDSM_X4(bl0, bl1, bl2, bl3, st + OFF_BL + off);
                #pragma unroll
                for (int mt = 0; mt < 2; mt++) {
                    MMA_BF16(cacc[mt][2 * ntp],     ah[mt], bh0, bh2);
                    MMA_BF16(cacc[mt][2 * ntp],     ah[mt], bl0, bl2);
                    MMA_BF16(cacc[mt][2 * ntp],     al[mt], bh0, bh2);
                    MMA_BF16(cacc[mt][2 * ntp + 1], ah[mt], bh1, bh3);
                    MMA_BF16(cacc[mt][2 * ntp + 1], ah[mt], bl1, bl3);
                    MMA_BF16(cacc[mt][2 * ntp + 1], al[mt], bh1, bh3);
                }
            }
        }
        __syncthreads();
    }

    // ---- epilogue ----
    #pragma unroll
    for (int mt = 0; mt < 2; mt++) {
        int row = m0 + wm + mt * 16 + (lane >> 2);
        #pragma unroll
        for (int nt = 0; nt < 8; nt++) {
            int col = n0 + wn + nt * 8 + ((lane & 3) << 1);
            float bx = bias[col], by = bias[col + 1];
            float v0 = (cacc[mt][nt][0] + bx) * scale;
            float v1 = (cacc[mt][nt][1] + by) * scale;
            float v2 = (cacc[mt][nt][2] + bx) * scale;
            float v3 = (cacc[mt][nt][3] + by) * scale;
            if (OSPLIT) {
                __nv_bfloat162 h01 = __floats2bfloat162_rn(v0, v1);
                __nv_bfloat162 h23 = __floats2bfloat162_rn(v2, v3);
                __nv_bfloat162 l01 = __floats2bfloat162_rn(
                    v0 - __bfloat162float(h01.x), v1 - __bfloat162float(h01.y));
                __nv_bfloat162 l23 = __floats2bfloat162_rn(
                    v2 - __bfloat162float(h23.x), v3 - __bfloat162float(h23.y));
                *(__nv_bfloat162*)&CHg[(size_t)row * N + col]       = h01;
                *(__nv_bfloat162*)&CHg[(size_t)(row + 8) * N + col] = h23;
                *(__nv_bfloat162*)&CLg[(size_t)row * N + col]       = l01;
                *(__nv_bfloat162*)&CLg[(size_t)(row + 8) * N + col] = l23;
            } else {
                float2 a = {v0, v1}, b = {v2, v3};
                *(float2*)&Cf[(size_t)row * N + col]       = a;
                *(float2*)&Cf[(size_t)(row + 8) * N + col] = b;
            }
        }
    }
}

// ---------------------------------------------------------------------------
// Flash attention, split-bf16 mma.sync, poly-exp softmax, cp.async 2-stage.
// ---------------------------------------------------------------------------
#define ASTG 32768
#define AOFF_KH 0
#define AOFF_KL 8192
#define AOFF_VH 16384
#define AOFF_VL 24576
#define ATTN_SMEM (2 * ASTG)

__device__ __forceinline__ void attn_prefetch(
    uint32_t sb, int stage, int tid, size_t rowbase,
    const __nv_bfloat16* KHg, const __nv_bfloat16* KLg,
    const __nv_bfloat16* VHg, const __nv_bfloat16* VLg)
{
    const uint32_t base = sb + stage * ASTG;
    #pragma unroll
    for (int it = 0; it < 4; it++) {
        int idx = it * 128 + tid;
        int j = idx >> 3, c8 = (idx & 7) << 3;
        size_t g = rowbase + (size_t)j * D_MODEL + c8;
        uint32_t off = j * 128 + ((((c8 >> 3) ^ (j & 7))) << 4);
        CP16(base + AOFF_KH + off, &KHg[g]);
        CP16(base + AOFF_KL + off, &KLg[g]);
        CP16(base + AOFF_VH + off, &VHg[g]);
        CP16(base + AOFF_VL + off, &VLg[g]);
    }
}

__global__ __launch_bounds__(128) void attn_mma_kernel(
    const __nv_bfloat16* __restrict__ QHg, const __nv_bfloat16* __restrict__ QLg,
    const __nv_bfloat16* __restrict__ KHg, const __nv_bfloat16* __restrict__ KLg,
    const __nv_bfloat16* __restrict__ VHg, const __nv_bfloat16* __restrict__ VLg,
    __nv_bfloat16* __restrict__ OH, __nv_bfloat16* __restrict__ OL)
{
    extern __shared__ char asm_[];
    const uint32_t sb = smem_u32(asm_);

    const int tid  = threadIdx.x;
    const int lane = tid & 31;
    const int warp = tid >> 5;
    const int tile = gridDim.x - 1 - blockIdx.x;
    const int h    = blockIdx.y;
    const int b    = blockIdx.z;
    const int base = b * SEQ;
    const int sel  = lane >> 3;
    const int l7   = lane & 7;
    const int wq   = warp * 16;

    // ---- stage Q into stage-1 KH/KL area, extract A-frags ----
    {
        const uint32_t qb = sb + ASTG;
        #pragma unroll
        for (int it = 0; it < 4; it++) {
            int idx = it * 128 + tid;
            int r = idx >> 3, c8 = (idx & 7) << 3;
            size_t g = (size_t)(base + tile * 64 + r) * D_MODEL + h * D_K + c8;
            uint32_t off = r * 128 + ((((c8 >> 3) ^ (r & 7))) << 4);
            CP16(qb + AOFF_KH + off, &QHg[g]);
            CP16(qb + AOFF_KL + off, &QLg[g]);
        }
        CP_COMMIT();
        CP_WAIT(0);
        __syncthreads();
    }
    uint32_t qh[4][4], ql[4][4];
    #pragma unroll
    for (int kc = 0; kc < 4; kc++) {
        uint32_t row = wq + ((sel & 1) << 3) + l7;
        uint32_t off = row * 128 + ((((uint32_t)(kc * 2 + (sel >> 1)) ^ (row & 7))) << 4);
        LDSM_X4(qh[kc][0], qh[kc][1], qh[kc][2], qh[kc][3], sb + ASTG + AOFF_KH + off);
        LDSM_X4(ql[kc][0], ql[kc][1], ql[kc][2], ql[kc][3], sb + ASTG + AOFF_KL + off);
    }
    __syncthreads();

    float oacc[8][4];
    #pragma unroll
    for (int ng = 0; ng < 8; ng++)
        #pragma unroll
        for (int i = 0; i < 4; i++) oacc[ng][i] = 0.f;
    float mrow[2] = {-1e30f, -1e30f};
    float lrow[2] = {0.f, 0.f};

    attn_prefetch(sb, 0, tid, (size_t)base * D_MODEL + h * D_K, KHg, KLg, VHg, VLg);
    CP_COMMIT();

    for (int t = 0; t <= tile; t++) {
        if (t < tile) {
            attn_prefetch(sb, (t + 1) & 1, tid,
                          (size_t)(base + (t + 1) * 64) * D_MODEL + h * D_K,
                          KHg, KLg, VHg, VLg);
            CP_COMMIT();
            CP_WAIT(1);
        } else {
            CP_WAIT(0);
        }
        __syncthreads();
        const uint32_t st = sb + (t & 1) * ASTG;

        // ---- S = Q @ K^T ----
        float sacc[8][4];
        #pragma unroll
        for (int nt = 0; nt < 8; nt++)
            #pragma unroll
            for (int i = 0; i < 4; i++) sacc[nt][i] = 0.f;

        #pragma unroll
        for (int kc = 0; kc < 4; kc++) {
            const uint32_t unit = kc * 2 + (sel >> 1);
            #pragma unroll
            for (int ntp = 0; ntp < 4; ntp++) {
                uint32_t rowB = ntp * 16 + ((sel & 1) << 3) + l7;
                uint32_t off  = rowB * 128 + ((unit ^ (rowB & 7)) << 4);
                uint32_t bh0, bh1, bh2, bh3, bl0, bl1, bl2, bl3;
                LDSM_X4(bh0, bh1, bh2, bh3, st + AOFF_KH + off);
                LDSM_X4(bl0, bl1, bl2, bl3, st + AOFF_KL + off);
                MMA_BF16(sacc[2 * ntp],     qh[kc], bh0, bh2);
                MMA_BF16(sacc[2 * ntp],     qh[kc], bl0, bl2);
                MMA_BF16(sacc[2 * ntp],     ql[kc], bh0, bh2);
                MMA_BF16(sacc[2 * ntp + 1], qh[kc], bh1, bh3);
                MMA_BF16(sacc[2 * ntp + 1], qh[kc], bl1, bl3);
                MMA_BF16(sacc[2 * ntp + 1], ql[kc], bh1, bh3);
            }
        }

        // ---- causal mask on diagonal tile ----
        if (t == tile) {
            int r0 = wq + (lane >> 2);
            #pragma unroll
            for (int nt = 0; nt < 8; nt++) {
                int cb = nt * 8 + ((lane & 3) << 1);
                if (cb     > r0)     sacc[nt][0] = -1e30f;
                if (cb + 1 > r0)     sacc[nt][1] = -1e30f;
                if (cb     > r0 + 8) sacc[nt][2] = -1e30f;
                if (cb + 1 > r0 + 8) sacc[nt][3] = -1e30f;
            }
        }

        // ---- online softmax ----
        #pragma unroll
        for (int ri = 0; ri < 2; ri++) {
            const int e0 = ri * 2, e1 = ri * 2 + 1;
            float rm = -1e30f;
            #pragma unroll
            for (int nt = 0; nt < 8; nt++)
                rm = fmaxf(rm, fmaxf(sacc[nt][e0], sacc[nt][e1]));
            rm = fmaxf(rm, __shfl_xor_sync(0xffffffffu, rm, 1));
            rm = fmaxf(rm, __shfl_xor_sync(0xffffffffu, rm, 2));
            float mn = fmaxf(mrow[ri], rm);
            float corr = fexp(mrow[ri] - mn);
            mrow[ri] = mn;
            lrow[ri] *= corr;
            #pragma unroll
            for (int ng = 0; ng < 8; ng++) {
                oacc[ng][e0] *= corr;
                oacc[ng][e1] *= corr;
            }
            float ls = 0.f;
            #pragma unroll
            for (int nt = 0; nt < 8; nt++) {
                float p0 = fexp(sacc[nt][e0] - mn);
                float p1 = fexp(sacc[nt][e1] - mn);
                sacc[nt][e0] = p0;
                sacc[nt][e1] = p1;
                ls += p0 + p1;
            }
            lrow[ri] += ls;
        }

        // ---- O += P @ V ----
        #pragma unroll
        for (int kc = 0; kc < 4; kc++) {
            uint32_t aH[4], aL[4];
            {
                float c0 = sacc[2 * kc][0],     c1 = sacc[2 * kc][1];
                float c2 = sacc[2 * kc][2],     c3 = sacc[2 * kc][3];
                float d0 = sacc[2 * kc + 1][0], d1 = sacc[2 * kc + 1][1];
                float d2 = sacc[2 * kc + 1][2], d3 = sacc[2 * kc + 1][3];
                aH[0] = pack_bf2(c0, c1);
                aH[1] = pack_bf2(c2, c3);
                aH[2] = pack_bf2(d0, d1);
                aH[3] = pack_bf2(d2, d3);
                __nv_bfloat162 h0 = *(__nv_bfloat162*)&aH[0];
                __nv_bfloat162 h1 = *(__nv_bfloat162*)&aH[1];
                __nv_bfloat162 h2 = *(__nv_bfloat162*)&aH[2];
                __nv_bfloat162 h3 = *(__nv_bfloat162*)&aH[3];
                aL[0] = pack_bf2(c0 - __bfloat162float(h0.x), c1 - __bfloat162float(h0.y));
                aL[1] = pack_bf2(c2 - __bfloat162float(h1.x), c3 - __bfloat162float(h1.y));
                aL[2] = pack_bf2(d0 - __bfloat162float(h2.x), d1 - __bfloat162float(h2.y));
                aL[3] = pack_bf2(d2 - __bfloat162float(h3.x), d3 - __bfloat162float(h3.y));
            }
            #pragma unroll
            for (int dp = 0; dp < 4; dp++) {
                uint32_t rowV = kc * 16 + ((sel & 1) << 3) + l7;
                uint32_t unit = dp * 2 + (sel >> 1);
                uint32_t off  = rowV * 128 + ((unit ^ (rowV & 7)) << 4);
                uint32_t vh0, vh1, vh2, vh3, vl0, vl1, vl2, vl3;
                LDSM_X4_T(vh0, vh1, vh2, vh3, st + AOFF_VH + off);
                LDSM_X4_T(vl0, vl1, vl2, vl3, st + AOFF_VL + off);
                MMA_BF16(oacc[2 * dp],     aH, vh0, vh1);
                MMA_BF16(oacc[2 * dp],     aH, vl0, vl1);
                MMA_BF16(oacc[2 * dp],     aL, vh0, vh1);
                MMA_BF16(oacc[2 * dp + 1], aH, vh2, vh3);
                MMA_BF16(oacc[2 * dp + 1], aH, vl2, vl3);
                MMA_BF16(oacc[2 * dp + 1], aL, vh2, vh3);
            }
        }
        __syncthreads();
    }

    // ---- finalize: split bf16 output ----
    #pragma unroll
    for (int ri = 0; ri < 2; ri++) {
        lrow[ri] += __shfl_xor_sync(0xffffffffu, lrow[ri], 1);
        lrow[ri] += __shfl_xor_sync(0xffffffffu, lrow[ri], 2);
    }
    float inv0 = 1.f / lrow[0], inv1 = 1.f / lrow[1];
    int row0 = base + tile * 64 + wq + (lane >> 2);
    #pragma unroll
    for (int ng = 0; ng < 8; ng++) {
        int col = h * D_K + ng * 8 + ((lane & 3) << 1);
        float v0 = oacc[ng][0] * inv0, v1 = oacc[ng][1] * inv0;
        float v2 = oacc[ng][2] * inv1, v3 = oacc[ng][3] * inv1;
        __nv_bfloat162 h01 = __floats2bfloat162_rn(v0, v1);
        __nv_bfloat162 h23 = __floats2bfloat162_rn(v2, v3);
        __nv_bfloat162 l01 = __floats2bfloat162_rn(
            v0 - __bfloat162float(h01.x), v1 - __bfloat162float(h01.y));
        __nv_bfloat162 l23 = __floats2bfloat162_rn(
            v2 - __bfloat162float(h23.x), v3 - __bfloat162float(h23.y));
        *(__nv_bfloat162*)&OH[(size_t)row0 * D_MODEL + col]       = h01;
        *(__nv_bfloat162*)&OH[(size_t)(row0 + 8) * D_MODEL + col] = h23;
        *(__nv_bfloat162*)&OL[(size_t)row0 * D_MODEL + col]       = l01;
        *(__nv_bfloat162*)&OL[(size_t)(row0 + 8) * D_MODEL + col] = l23;
    }
}

// ---------------------------------------------------------------------------
// Launch
// ---------------------------------------------------------------------------
extern "C" void kernel_launch(void* const* d_in, const int* in_sizes, int n_in,
                              void* d_out, int out_size)
{
    const float* queries = (const float*)d_in[0];
    const float* keys    = (const float*)d_in[1];
    // d_in[2] = values (unused by reference)
    const float* Wq = (const float*)d_in[3];
    const float* bq = (const float*)d_in[4];
    const float* Wd = (const float*)d_in[5];
    const float* bd = (const float*)d_in[6];
    const float* Wk = (const float*)d_in[7];
    const float* bk = (const float*)d_in[8];
    const float* Wv = (const float*)d_in[9];
    const float* bv = (const float*)d_in[10];
    const float* Wo = (const float*)d_in[11];
    const float* bo = (const float*)d_in[12];
    float* out = (float*)d_out;

    __nv_bfloat16 *pQinH, *pQinL, *pKinH, *pKinL;
    __nv_bfloat16 *pLatH, *pLatL, *pQH, *pQL, *pKH, *pKL, *pVH, *pVL, *pOH, *pOL;
    __nv_bfloat16 *pWqTH, *pWqTL, *pWdTH, *pWdTL, *pWkTH, *pWkTL, *pWvTH, *pWvTL, *pWoTH, *pWoTL;
    cudaGetSymbolAddress((void**)&pQinH, g_qinH);
    cudaGetSymbolAddress((void**)&pQinL, g_qinL);
    cudaGetSymbolAddress((void**)&pKinH, g_kinH);
    cudaGetSymbolAddress((void**)&pKinL, g_kinL);
    cudaGetSymbolAddress((void**)&pLatH, g_latH);
    cudaGetSymbolAddress((void**)&pLatL, g_latL);
    cudaGetSymbolAddress((void**)&pQH, g_QH);
    cudaGetSymbolAddress((void**)&pQL, g_QL);
    cudaGetSymbolAddress((void**)&pKH, g_KH);
    cudaGetSymbolAddress((void**)&pKL, g_KL);
    cudaGetSymbolAddress((void**)&pVH, g_VH);
    cudaGetSymbolAddress((void**)&pVL, g_VL);
    cudaGetSymbolAddress((void**)&pOH, g_OH);
    cudaGetSymbolAddress((void**)&pOL, g_OL);
    cudaGetSymbolAddress((void**)&pWqTH, g_WqTH);
    cudaGetSymbolAddress((void**)&pWqTL, g_WqTL);
    cudaGetSymbolAddress((void**)&pWdTH, g_WdTH);
    cudaGetSymbolAddress((void**)&pWdTL, g_WdTL);
    cudaGetSymbolAddress((void**)&pWkTH, g_WkTH);
    cudaGetSymbolAddress((void**)&pWkTL, g_WkTL);
    cudaGetSymbolAddress((void**)&pWvTH, g_WvTH);
    cudaGetSymbolAddress((void**)&pWvTL, g_WvTL);
    cudaGetSymbolAddress((void**)&pWoTH, g_WoTH);
    cudaGetSymbolAddress((void**)&pWoTL, g_WoTL);

    cudaFuncSetAttribute(gemm_dual<true>,
                         cudaFuncAttributeMaxDynamicSharedMemorySize, GEMM_SMEM);
    cudaFuncSetAttribute(gemm_dual<false>,
                         cudaFuncAttributeMaxDynamicSharedMemorySize, GEMM_SMEM);
    cudaFuncSetAttribute(attn_mma_kernel,
                         cudaFuncAttributeMaxDynamicSharedMemorySize, ATTN_SMEM);

    // 0) fused preprocessing (input splits + weight transpose-splits)
    preproc_kernel<<<4864, 256>>>(
        queries, keys, Wq, Wd, Wk, Wv, Wo,
        pQinH, pQinL, pKinH, pKinL,
        pWqTH, pWqTL, pWdTH, pWdTL, pWkTH, pWkTL,
        pWvTH, pWvTL, pWoTH, pWoTL);

    // 1+2) latent = keys @ Wd + bd  ||  Q = (queries @ Wq + bq) * 0.125
    gemm_dual<true><<<dim3(2 + 8, ROWS / 128), 256, GEMM_SMEM>>>(
        2,
        pKinH, pKinL, pWdTH, pWdTL, bd, 1.f,    nullptr, pLatH, pLatL, LATENT, D_MODEL,
        pQinH, pQinL, pWqTH, pWqTL, bq, 0.125f, nullptr, pQH,   pQL,   D_MODEL, D_MODEL);

    // 3+4) K = latent @ Wk + bk  ||  V = latent @ Wv + bv
    gemm_dual<true><<<dim3(8 + 8, ROWS / 128), 256, GEMM_SMEM>>>(
        8,
        pLatH, pLatL, pWkTH, pWkTL, bk, 1.f, nullptr, pKH, pKL, D_MODEL, LATENT,
        pLatH, pLatL, pWvTH, pWvTL, bv, 1.f, nullptr, pVH, pVL, D_MODEL, LATENT);

    // 5) attention (split output)
    attn_mma_kernel<<<dim3(SEQ / 64, N_HEADS, BATCH), 128, ATTN_SMEM>>>(
        pQH, pQL, pKH, pKL, pVH, pVL, pOH, pOL);

    // 6) out = O @ Wo + bo
    gemm_dual<false><<<dim3(8, ROWS / 128), 256, GEMM_SMEM>>>(
        8,
        pOH, pOL, pWoTH, pWoTL, bo, 1.f, out, nullptr, nullptr, D_MODEL, D_MODEL,
        pOH, pOL, pWoTH, pWoTL, bo, 1.f, out, nullptr, nullptr, D_MODEL, D_MODEL);
}